// round 1
// baseline (speedup 1.0000x reference)
#include <cuda_runtime.h>
#include <cuda_bf16.h>

#define NN   50000
#define EE   800000
#define FIN  128
#define D0   256
#define DIMV 64
#define GG   256
#define OUTW 320   // D0 + DIMV

// ---------------- scratch (device globals; no allocation) ----------------
__device__ float    g_q[NN * D0];
__device__ float    g_k[NN * D0];
__device__ float    g_v[NN * D0];
__device__ float    g_o[NN * D0];
__device__ float    g_h[NN * D0];      // normalized layer-0 output (layer-1 input)
__device__ float    g_logit[EE];       // logits, then p (reused)
__device__ float    g_s[NN];           // softmax denominators
__device__ unsigned g_m[NN];           // segment max (order-preserving uint encoding)
__device__ float    g_stats[2 * D0];   // per-column sum / sumsq -> mu / rsigma
__device__ float    g_cnt[GG];         // nodes per graph

// ---------------- helpers ----------------
__device__ __forceinline__ unsigned f2o(float f) {
    unsigned u = __float_as_uint(f);
    return (u >> 31) ? ~u : (u | 0x80000000u);
}
__device__ __forceinline__ float o2f(unsigned u) {
    return __uint_as_float((u >> 31) ? (u ^ 0x80000000u) : ~u);
}

// ---------------- init kernels ----------------
__global__ void init_global(float* pool, float* cnt) {
    int i = blockIdx.x * blockDim.x + threadIdx.x;
    if (i < GG * OUTW) pool[i] = 0.f;
    if (i < GG) cnt[i] = 0.f;
}
__global__ void init_layer(float* s, unsigned* m, float* stats) {
    int i = blockIdx.x * blockDim.x + threadIdx.x;
    if (i < NN) { s[i] = 0.f; m[i] = 0u; }
    if (i < 2 * D0) stats[i] = 0.f;
}
__global__ void count_kernel(const int* __restrict__ batch, float* cnt) {
    int i = blockIdx.x * blockDim.x + threadIdx.x;
    if (i < NN) atomicAdd(&cnt[batch[i]], 1.f);
}

// ---------------- SGEMM: C[M,Nc] = A[M,K] @ W[K,Nc] + bias ----------------
// 64x64 tile, TK=16, 256 threads, 4x4 microtile per thread.
__global__ void sgemm_bias(const float* __restrict__ A, const float* __restrict__ W,
                           const float* __restrict__ bias, float* __restrict__ C,
                           int M, int K, int Nc) {
    __shared__ float As[16][65];
    __shared__ float Bs[16][64];
    int t = threadIdx.x;
    int row0 = blockIdx.y * 64;
    int col0 = blockIdx.x * 64;
    int tx = t & 15, ty = t >> 4;
    float acc[4][4] = {};

    for (int k0 = 0; k0 < K; k0 += 16) {
        #pragma unroll
        for (int i = 0; i < 4; i++) {          // A tile: 64 rows x 16 k
            int idx = t + 256 * i;
            int kk = idx & 15, mrow = idx >> 4;
            int r = row0 + mrow;
            As[kk][mrow] = (r < M) ? A[r * K + k0 + kk] : 0.f;
        }
        #pragma unroll
        for (int i = 0; i < 4; i++) {          // B tile: 16 k x 64 cols
            int idx = t + 256 * i;
            int n = idx & 63, kk = idx >> 6;
            Bs[kk][n] = W[(k0 + kk) * Nc + col0 + n];
        }
        __syncthreads();
        #pragma unroll
        for (int kk = 0; kk < 16; kk++) {
            float a[4], b[4];
            #pragma unroll
            for (int i = 0; i < 4; i++) a[i] = As[kk][ty + 16 * i];
            #pragma unroll
            for (int j = 0; j < 4; j++) b[j] = Bs[kk][tx + 16 * j];
            #pragma unroll
            for (int i = 0; i < 4; i++)
                #pragma unroll
                for (int j = 0; j < 4; j++) acc[i][j] += a[i] * b[j];
        }
        __syncthreads();
    }
    #pragma unroll
    for (int i = 0; i < 4; i++) {
        int r = row0 + ty + 16 * i;
        if (r >= M) continue;
        #pragma unroll
        for (int j = 0; j < 4; j++) {
            int c = col0 + tx + 16 * j;
            C[r * Nc + c] = acc[i][j] + bias[c];
        }
    }
}

// ---------------- edge kernels (warp per edge) ----------------
__global__ void edge_logits(const float* __restrict__ q, const float* __restrict__ k,
                            const int* __restrict__ ei, const float* __restrict__ ea,
                            const float* __restrict__ We, float* __restrict__ logit,
                            unsigned* __restrict__ m, int D, float scale) {
    int gt = blockIdx.x * blockDim.x + threadIdx.x;
    int e = gt >> 5;
    int lane = gt & 31;
    if (e >= EE) return;
    int src = ei[e];
    int dst = ei[EE + e];
    float a = ea[e];
    float sum = 0.f;
    for (int f = lane; f < D; f += 32)
        sum += q[dst * D + f] * (k[src * D + f] + a * We[f]);
    #pragma unroll
    for (int off = 16; off > 0; off >>= 1)
        sum += __shfl_xor_sync(0xffffffffu, sum, off);
    if (lane == 0) {
        float l = sum * scale;
        logit[e] = l;
        atomicMax(&m[dst], f2o(l));
    }
}

__global__ void edge_p(float* __restrict__ logit, const unsigned* __restrict__ m,
                       const int* __restrict__ ei, float* __restrict__ s) {
    int e = blockIdx.x * blockDim.x + threadIdx.x;
    if (e >= EE) return;
    int dst = ei[EE + e];
    float p = expf(logit[e] - o2f(m[dst]));
    logit[e] = p;
    atomicAdd(&s[dst], p);
}

__global__ void edge_scatter(const float* __restrict__ v, float* __restrict__ o,
                             const int* __restrict__ ei, const float* __restrict__ ea,
                             const float* __restrict__ We, const float* __restrict__ p,
                             const float* __restrict__ s, int D) {
    int gt = blockIdx.x * blockDim.x + threadIdx.x;
    int e = gt >> 5;
    int lane = gt & 31;
    if (e >= EE) return;
    int src = ei[e];
    int dst = ei[EE + e];
    float a = ea[e];
    float alpha = p[e] / (s[dst] + 1e-16f);
    for (int f = lane; f < D; f += 32)
        atomicAdd(&o[dst * D + f], (v[src * D + f] + a * We[f]) * alpha);
}

// ---------------- batch norm ----------------
__global__ void bn_stats(const float* __restrict__ X, float* __restrict__ stats,
                         int Nrows, int D) {
    int c = threadIdx.x;  // blockDim.x == D
    float su = 0.f, sq = 0.f;
    for (int r = blockIdx.x; r < Nrows; r += gridDim.x) {
        float v = X[r * D + c];
        su += v;
        sq += v * v;
    }
    atomicAdd(&stats[c], su);
    atomicAdd(&stats[D + c], sq);
}

__global__ void bn_finalize(float* stats, int Nrows, int D) {
    int c = threadIdx.x;
    if (c >= D) return;
    float mu = stats[c] / (float)Nrows;
    float var = stats[D + c] / (float)Nrows - mu * mu;
    stats[c] = mu;
    stats[D + c] = rsqrtf(var + 1e-5f);
}

// normalize; write h (optional), xs slab, and accumulate pool
__global__ void bn_apply(const float* __restrict__ X, const float* __restrict__ stats,
                         const float* __restrict__ gamma, const float* __restrict__ beta,
                         float* __restrict__ h, float* __restrict__ xs,
                         float* __restrict__ pool, const int* __restrict__ batch,
                         int Nrows, int D, int col_off) {
    int idx = blockIdx.x * blockDim.x + threadIdx.x;
    if (idx >= Nrows * D) return;
    int r = idx / D, c = idx % D;
    float val = gamma[c] * (X[idx] - stats[c]) * stats[D + c] + beta[c];
    if (h) h[idx] = val;
    xs[r * OUTW + col_off + c] = val;
    atomicAdd(&pool[batch[r] * OUTW + col_off + c], val);
}

__global__ void pool_div(float* pool, const float* __restrict__ cnt) {
    int i = blockIdx.x * blockDim.x + threadIdx.x;
    if (i >= GG * OUTW) return;
    pool[i] /= fmaxf(cnt[i / OUTW], 1.f);
}

// ---------------- launch ----------------
extern "C" void kernel_launch(void* const* d_in, const int* in_sizes, int n_in,
                              void* d_out, int out_size) {
    const float* x     = (const float*)d_in[0];
    const int*   ei    = (const int*)  d_in[1];
    const float* ea    = (const float*)d_in[2];
    const int*   batch = (const int*)  d_in[3];
    const float* Wq0 = (const float*)d_in[4];  const float* bq0 = (const float*)d_in[5];
    const float* Wk0 = (const float*)d_in[6];  const float* bk0 = (const float*)d_in[7];
    const float* Wv0 = (const float*)d_in[8];  const float* bv0 = (const float*)d_in[9];
    const float* We0 = (const float*)d_in[10];
    const float* Ws0 = (const float*)d_in[11]; const float* bs0 = (const float*)d_in[12];
    const float* gamma0 = (const float*)d_in[13]; const float* beta0 = (const float*)d_in[14];
    const float* Wq1 = (const float*)d_in[15]; const float* bq1 = (const float*)d_in[16];
    const float* Wk1 = (const float*)d_in[17]; const float* bk1 = (const float*)d_in[18];
    const float* Wv1 = (const float*)d_in[19]; const float* bv1 = (const float*)d_in[20];
    const float* We1 = (const float*)d_in[21];
    const float* Ws1 = (const float*)d_in[22]; const float* bs1 = (const float*)d_in[23];
    const float* gamma1 = (const float*)d_in[24]; const float* beta1 = (const float*)d_in[25];

    float* out  = (float*)d_out;
    float* pool = out;               // [G, 320]
    float* xs   = out + GG * OUTW;   // [N, 320]

    float *q, *k, *v, *o, *h, *logit, *s, *stats, *cnt;
    unsigned* m;
    cudaGetSymbolAddress((void**)&q, g_q);
    cudaGetSymbolAddress((void**)&k, g_k);
    cudaGetSymbolAddress((void**)&v, g_v);
    cudaGetSymbolAddress((void**)&o, g_o);
    cudaGetSymbolAddress((void**)&h, g_h);
    cudaGetSymbolAddress((void**)&logit, g_logit);
    cudaGetSymbolAddress((void**)&s, g_s);
    cudaGetSymbolAddress((void**)&m, g_m);
    cudaGetSymbolAddress((void**)&stats, g_stats);
    cudaGetSymbolAddress((void**)&cnt, g_cnt);

    const int TB = 256;
    int nb_nodes = (NN + TB - 1) / TB;
    int nb_edges_warp = (EE * 32 + TB - 1) / TB;
    int nb_edges = (EE + TB - 1) / TB;

    // global init
    init_global<<<(GG * OUTW + TB - 1) / TB, TB>>>(pool, cnt);
    init_layer<<<nb_nodes, TB>>>(s, m, stats);
    count_kernel<<<nb_nodes, TB>>>(batch, cnt);

    // ---------- layer 0 ----------
    dim3 g0(D0 / 64, (NN + 63) / 64);
    sgemm_bias<<<g0, 256>>>(x, Wq0, bq0, q, NN, FIN, D0);
    sgemm_bias<<<g0, 256>>>(x, Wk0, bk0, k, NN, FIN, D0);
    sgemm_bias<<<g0, 256>>>(x, Wv0, bv0, v, NN, FIN, D0);
    sgemm_bias<<<g0, 256>>>(x, Ws0, bs0, o, NN, FIN, D0);  // skip lands in o

    edge_logits<<<nb_edges_warp, TB>>>(q, k, ei, ea, We0, logit, m, D0, 1.f / 16.f);
    edge_p<<<nb_edges, TB>>>(logit, m, ei, s);
    edge_scatter<<<nb_edges_warp, TB>>>(v, o, ei, ea, We0, logit, s, D0);

    bn_stats<<<256, D0>>>(o, stats, NN, D0);
    bn_finalize<<<1, D0>>>(stats, NN, D0);
    bn_apply<<<(NN * D0 + TB - 1) / TB, TB>>>(o, stats, gamma0, beta0, h, xs, pool, batch,
                                              NN, D0, 0);

    // ---------- layer 1 ----------
    init_layer<<<nb_nodes, TB>>>(s, m, stats);

    dim3 g1(DIMV / 64, (NN + 63) / 64);
    sgemm_bias<<<g1, 256>>>(h, Wq1, bq1, q, NN, D0, DIMV);
    sgemm_bias<<<g1, 256>>>(h, Wk1, bk1, k, NN, D0, DIMV);
    sgemm_bias<<<g1, 256>>>(h, Wv1, bv1, v, NN, D0, DIMV);
    sgemm_bias<<<g1, 256>>>(h, Ws1, bs1, o, NN, D0, DIMV);

    edge_logits<<<nb_edges_warp, TB>>>(q, k, ei, ea, We1, logit, m, DIMV, 1.f / 8.f);
    edge_p<<<nb_edges, TB>>>(logit, m, ei, s);
    edge_scatter<<<nb_edges_warp, TB>>>(v, o, ei, ea, We1, logit, s, DIMV);

    bn_stats<<<256, DIMV>>>(o, stats, NN, DIMV);
    bn_finalize<<<1, DIMV>>>(stats, NN, DIMV);
    bn_apply<<<(NN * DIMV + TB - 1) / TB, TB>>>(o, stats, gamma1, beta1, nullptr, xs, pool,
                                                batch, NN, DIMV, D0);

    pool_div<<<(GG * OUTW + TB - 1) / TB, TB>>>(pool, cnt);
}

// round 2
// speedup vs baseline: 1.5740x; 1.5740x over previous
#include <cuda_runtime.h>
#include <cuda_bf16.h>

#define NN   50000
#define EE   800000
#define FIN  128
#define D0   256
#define DIMV 64
#define GG   256
#define OUTW 320   // D0 + DIMV

// ---------------- scratch (device globals; no allocation) ----------------
__device__ float g_q[NN * D0];
__device__ float g_k[NN * D0];
__device__ float g_v[NN * D0];
__device__ float g_o[NN * D0];
__device__ float g_h[NN * D0];        // normalized layer-0 output (layer-1 input)
__device__ float g_p[EE];             // softmax numerators
__device__ float g_s[NN];             // softmax denominators
__device__ float g_stats[2 * D0];     // per-column sum/sumsq -> mu/rsigma
__device__ float g_cnt[GG];           // nodes per graph
__device__ float g_Wp0[FIN * 4 * D0]; // packed layer-0 weights [128,1024]
__device__ float g_bp0[4 * D0];
__device__ float g_Wp1[D0 * 4 * DIMV]; // packed layer-1 weights [256,256]
__device__ float g_bp1[4 * DIMV];

// ---------------- helpers ----------------
__device__ __forceinline__ void red_add_v4(float* ptr, float4 v) {
    asm volatile("red.global.add.v4.f32 [%0], {%1,%2,%3,%4};"
                 :: "l"(ptr), "f"(v.x), "f"(v.y), "f"(v.z), "f"(v.w) : "memory");
}

// ---------------- init / pack kernels ----------------
__global__ void init_global(float* pool, float* cnt) {
    int i = blockIdx.x * blockDim.x + threadIdx.x;
    if (i < GG * OUTW) pool[i] = 0.f;
    if (i < GG) cnt[i] = 0.f;
}
__global__ void init_layer(float* s, float* stats) {
    int i = blockIdx.x * blockDim.x + threadIdx.x;
    if (i < NN) s[i] = 0.f;
    if (i < 2 * D0) stats[i] = 0.f;
}
__global__ void count_kernel(const int* __restrict__ batch, float* cnt) {
    int i = blockIdx.x * blockDim.x + threadIdx.x;
    if (i < NN) atomicAdd(&cnt[batch[i]], 1.f);
}
__global__ void pack_w(const float* __restrict__ W0, const float* __restrict__ W1,
                       const float* __restrict__ W2, const float* __restrict__ W3,
                       const float* __restrict__ b0, const float* __restrict__ b1,
                       const float* __restrict__ b2, const float* __restrict__ b3,
                       float* __restrict__ Wp, float* __restrict__ bp, int K, int D) {
    int Nc = 4 * D;
    int i = blockIdx.x * blockDim.x + threadIdx.x;
    if (i < K * Nc) {
        int k = i / Nc, c = i % Nc;
        int sel = c / D, cc = c % D;
        const float* W = sel == 0 ? W0 : sel == 1 ? W1 : sel == 2 ? W2 : W3;
        Wp[i] = W[k * D + cc];
    }
    if (i < Nc) {
        int sel = i / D, cc = i % D;
        const float* b = sel == 0 ? b0 : sel == 1 ? b1 : sel == 2 ? b2 : b3;
        bp[i] = b[cc];
    }
}

// ---------------- SGEMM: 128x64 tile, TK=16, 256 threads, 8x4 microtile --------
// Computes [M, 4D] = A[M,K] @ Wp[K,4D] + bp, demuxing column groups of D into
// four separate output buffers.
__global__ void sgemm4(const float* __restrict__ A, const float* __restrict__ Wp,
                       const float* __restrict__ bp,
                       float* __restrict__ O0, float* __restrict__ O1,
                       float* __restrict__ O2, float* __restrict__ O3,
                       int M, int K, int D) {
    const int Nc = 4 * D;
    __shared__ __align__(16) float As[16][132];
    __shared__ __align__(16) float Bs[16][64];
    int t = threadIdx.x;
    int row0 = blockIdx.y * 128;
    int col0 = blockIdx.x * 64;
    int tx = t & 15, ty = t >> 4;
    float acc[8][4] = {};

    for (int k0 = 0; k0 < K; k0 += 16) {
        // A tile: 128 rows x 16 k = 512 float4, 2 per thread (transposed store)
        #pragma unroll
        for (int i = 0; i < 2; i++) {
            int idx = t + 256 * i;
            int r = idx >> 2, c4 = (idx & 3) * 4;
            int gr = row0 + r;
            float4 av = (gr < M) ? *(const float4*)&A[gr * K + k0 + c4]
                                 : make_float4(0.f, 0.f, 0.f, 0.f);
            As[c4 + 0][r] = av.x; As[c4 + 1][r] = av.y;
            As[c4 + 2][r] = av.z; As[c4 + 3][r] = av.w;
        }
        // B tile: 16 k x 64 cols = 256 float4, 1 per thread
        {
            int kk = t >> 4, n4 = (t & 15) * 4;
            *(float4*)&Bs[kk][n4] = *(const float4*)&Wp[(k0 + kk) * Nc + col0 + n4];
        }
        __syncthreads();
        #pragma unroll
        for (int kk = 0; kk < 16; kk++) {
            float a[8], b[4];
            *(float4*)&a[0] = *(const float4*)&As[kk][ty * 8];
            *(float4*)&a[4] = *(const float4*)&As[kk][ty * 8 + 4];
            *(float4*)&b[0] = *(const float4*)&Bs[kk][tx * 4];
            #pragma unroll
            for (int i = 0; i < 8; i++)
                #pragma unroll
                for (int j = 0; j < 4; j++)
                    acc[i][j] += a[i] * b[j];
        }
        __syncthreads();
    }

    int sel = col0 / D;
    float* O = sel == 0 ? O0 : sel == 1 ? O1 : sel == 2 ? O2 : O3;
    int cc0 = (col0 % D) + tx * 4;
    float4 bias = *(const float4*)&bp[col0 + tx * 4];
    #pragma unroll
    for (int i = 0; i < 8; i++) {
        int r = row0 + ty * 8 + i;
        if (r >= M) continue;
        float4 ov;
        ov.x = acc[i][0] + bias.x; ov.y = acc[i][1] + bias.y;
        ov.z = acc[i][2] + bias.z; ov.w = acc[i][3] + bias.w;
        *(float4*)&O[r * D + cc0] = ov;
    }
}

// ---------------- edge kernels ----------------
// GROUP lanes cooperate on one edge; D = GROUP*4*NIT.
template <int GROUP, int NIT>
__global__ void edge_lp(const float* __restrict__ q, const float* __restrict__ k,
                        const int* __restrict__ ei, const float* __restrict__ ea,
                        const float* __restrict__ We, float* __restrict__ p,
                        float* __restrict__ s, float scale) {
    const int D = GROUP * 4 * NIT;
    int gt = blockIdx.x * blockDim.x + threadIdx.x;
    int e = gt / GROUP;
    int sl = gt % GROUP;
    if (e >= EE) return;
    int src = ei[e];
    int dst = ei[EE + e];
    float a = ea[e];
    float sum = 0.f;
    #pragma unroll
    for (int it = 0; it < NIT; it++) {
        int f = (it * GROUP + sl) * 4;
        float4 qv = *(const float4*)&q[dst * D + f];
        float4 kv = *(const float4*)&k[src * D + f];
        float4 wv = *(const float4*)&We[f];
        sum += qv.x * fmaf(a, wv.x, kv.x) + qv.y * fmaf(a, wv.y, kv.y)
             + qv.z * fmaf(a, wv.z, kv.z) + qv.w * fmaf(a, wv.w, kv.w);
    }
    #pragma unroll
    for (int off = GROUP / 2; off > 0; off >>= 1)
        sum += __shfl_xor_sync(0xffffffffu, sum, off);
    if (sl == 0) {
        float pe = expf(sum * scale);
        p[e] = pe;
        atomicAdd(&s[dst], pe);
    }
}

template <int GROUP, int NIT>
__global__ void edge_scatter(const float* __restrict__ v, float* __restrict__ o,
                             const int* __restrict__ ei, const float* __restrict__ ea,
                             const float* __restrict__ We, const float* __restrict__ p,
                             const float* __restrict__ s) {
    const int D = GROUP * 4 * NIT;
    int gt = blockIdx.x * blockDim.x + threadIdx.x;
    int e = gt / GROUP;
    int sl = gt % GROUP;
    if (e >= EE) return;
    int src = ei[e];
    int dst = ei[EE + e];
    float a = ea[e];
    float alpha = p[e] / (s[dst] + 1e-16f);
    #pragma unroll
    for (int it = 0; it < NIT; it++) {
        int f = (it * GROUP + sl) * 4;
        float4 vv = *(const float4*)&v[src * D + f];
        float4 wv = *(const float4*)&We[f];
        float4 msg;
        msg.x = fmaf(a, wv.x, vv.x) * alpha;
        msg.y = fmaf(a, wv.y, vv.y) * alpha;
        msg.z = fmaf(a, wv.z, vv.z) * alpha;
        msg.w = fmaf(a, wv.w, vv.w) * alpha;
        red_add_v4(&o[dst * D + f], msg);
    }
}

// ---------------- batch norm ----------------
__global__ void bn_stats(const float* __restrict__ X, float* __restrict__ stats,
                         int Nrows, int D) {
    int c = threadIdx.x;  // blockDim.x == D
    float su = 0.f, sq = 0.f;
    for (int r = blockIdx.x; r < Nrows; r += gridDim.x) {
        float v = X[r * D + c];
        su += v;
        sq += v * v;
    }
    atomicAdd(&stats[c], su);
    atomicAdd(&stats[D + c], sq);
}

__global__ void bn_finalize(float* stats, int Nrows, int D) {
    int c = threadIdx.x;
    if (c >= D) return;
    float mu = stats[c] / (float)Nrows;
    float var = stats[D + c] / (float)Nrows - mu * mu;
    stats[c] = mu;
    stats[D + c] = rsqrtf(var + 1e-5f);
}

// normalize; write h (optional), xs slab, accumulate pool (vectorized)
__global__ void bn_apply(const float* __restrict__ X, const float* __restrict__ stats,
                         const float* __restrict__ gamma, const float* __restrict__ beta,
                         float* __restrict__ h, float* __restrict__ xs,
                         float* __restrict__ pool, const int* __restrict__ batch,
                         int Nrows, int D, int col_off) {
    int idx = blockIdx.x * blockDim.x + threadIdx.x;
    int Dq = D >> 2;
    if (idx >= Nrows * Dq) return;
    int r = idx / Dq, c4 = (idx % Dq) * 4;
    float4 xv = *(const float4*)&X[r * D + c4];
    float4 mu = *(const float4*)&stats[c4];
    float4 rs = *(const float4*)&stats[D + c4];
    float4 gm = *(const float4*)&gamma[c4];
    float4 bt = *(const float4*)&beta[c4];
    float4 val;
    val.x = gm.x * (xv.x - mu.x) * rs.x + bt.x;
    val.y = gm.y * (xv.y - mu.y) * rs.y + bt.y;
    val.z = gm.z * (xv.z - mu.z) * rs.z + bt.z;
    val.w = gm.w * (xv.w - mu.w) * rs.w + bt.w;
    if (h) *(float4*)&h[r * D + c4] = val;
    *(float4*)&xs[r * OUTW + col_off + c4] = val;
    red_add_v4(&pool[batch[r] * OUTW + col_off + c4], val);
}

__global__ void pool_div(float* pool, const float* __restrict__ cnt) {
    int i = blockIdx.x * blockDim.x + threadIdx.x;
    if (i >= GG * OUTW) return;
    pool[i] /= fmaxf(cnt[i / OUTW], 1.f);
}

// ---------------- launch ----------------
extern "C" void kernel_launch(void* const* d_in, const int* in_sizes, int n_in,
                              void* d_out, int out_size) {
    const float* x     = (const float*)d_in[0];
    const int*   ei    = (const int*)  d_in[1];
    const float* ea    = (const float*)d_in[2];
    const int*   batch = (const int*)  d_in[3];
    const float* Wq0 = (const float*)d_in[4];  const float* bq0 = (const float*)d_in[5];
    const float* Wk0 = (const float*)d_in[6];  const float* bk0 = (const float*)d_in[7];
    const float* Wv0 = (const float*)d_in[8];  const float* bv0 = (const float*)d_in[9];
    const float* We0 = (const float*)d_in[10];
    const float* Ws0 = (const float*)d_in[11]; const float* bs0 = (const float*)d_in[12];
    const float* gamma0 = (const float*)d_in[13]; const float* beta0 = (const float*)d_in[14];
    const float* Wq1 = (const float*)d_in[15]; const float* bq1 = (const float*)d_in[16];
    const float* Wk1 = (const float*)d_in[17]; const float* bk1 = (const float*)d_in[18];
    const float* Wv1 = (const float*)d_in[19]; const float* bv1 = (const float*)d_in[20];
    const float* We1 = (const float*)d_in[21];
    const float* Ws1 = (const float*)d_in[22]; const float* bs1 = (const float*)d_in[23];
    const float* gamma1 = (const float*)d_in[24]; const float* beta1 = (const float*)d_in[25];

    float* out  = (float*)d_out;
    float* pool = out;               // [G, 320]
    float* xs   = out + GG * OUTW;   // [N, 320]

    float *q, *k, *v, *o, *h, *p, *s, *stats, *cnt, *Wp0, *bp0, *Wp1, *bp1;
    cudaGetSymbolAddress((void**)&q, g_q);
    cudaGetSymbolAddress((void**)&k, g_k);
    cudaGetSymbolAddress((void**)&v, g_v);
    cudaGetSymbolAddress((void**)&o, g_o);
    cudaGetSymbolAddress((void**)&h, g_h);
    cudaGetSymbolAddress((void**)&p, g_p);
    cudaGetSymbolAddress((void**)&s, g_s);
    cudaGetSymbolAddress((void**)&stats, g_stats);
    cudaGetSymbolAddress((void**)&cnt, g_cnt);
    cudaGetSymbolAddress((void**)&Wp0, g_Wp0);
    cudaGetSymbolAddress((void**)&bp0, g_bp0);
    cudaGetSymbolAddress((void**)&Wp1, g_Wp1);
    cudaGetSymbolAddress((void**)&bp1, g_bp1);

    const int TB = 256;
    int nb_nodes = (NN + TB - 1) / TB;

    // global init + weight packing
    init_global<<<(GG * OUTW + TB - 1) / TB, TB>>>(pool, cnt);
    init_layer<<<nb_nodes, TB>>>(s, stats);
    count_kernel<<<nb_nodes, TB>>>(batch, cnt);
    pack_w<<<(FIN * 4 * D0 + TB - 1) / TB, TB>>>(Wq0, Wk0, Wv0, Ws0, bq0, bk0, bv0, bs0,
                                                 Wp0, bp0, FIN, D0);
    pack_w<<<(D0 * 4 * DIMV + TB - 1) / TB, TB>>>(Wq1, Wk1, Wv1, Ws1, bq1, bk1, bv1, bs1,
                                                  Wp1, bp1, D0, DIMV);

    // ---------- layer 0 ----------
    dim3 g0(4 * D0 / 64, (NN + 127) / 128);
    sgemm4<<<g0, 256>>>(x, Wp0, bp0, q, k, v, o, NN, FIN, D0);  // skip lands in o

    edge_lp<32, 2><<<(EE * 32 + TB - 1) / TB, TB>>>(q, k, ei, ea, We0, p, s, 1.f / 16.f);
    edge_scatter<32, 2><<<(EE * 32 + TB - 1) / TB, TB>>>(v, o, ei, ea, We0, p, s);

    bn_stats<<<256, D0>>>(o, stats, NN, D0);
    bn_finalize<<<1, D0>>>(stats, NN, D0);
    bn_apply<<<(NN * D0 / 4 + TB - 1) / TB, TB>>>(o, stats, gamma0, beta0, h, xs, pool,
                                                  batch, NN, D0, 0);

    // ---------- layer 1 ----------
    init_layer<<<nb_nodes, TB>>>(s, stats);

    dim3 g1(4 * DIMV / 64, (NN + 127) / 128);
    sgemm4<<<g1, 256>>>(h, Wp1, bp1, q, k, v, o, NN, D0, DIMV);

    edge_lp<16, 1><<<(EE * 16 + TB - 1) / TB, TB>>>(q, k, ei, ea, We1, p, s, 1.f / 8.f);
    edge_scatter<16, 1><<<(EE * 16 + TB - 1) / TB, TB>>>(v, o, ei, ea, We1, p, s);

    bn_stats<<<256, DIMV>>>(o, stats, NN, DIMV);
    bn_finalize<<<1, DIMV>>>(stats, NN, DIMV);
    bn_apply<<<(NN * DIMV / 4 + TB - 1) / TB, TB>>>(o, stats, gamma1, beta1, nullptr, xs,
                                                    pool, batch, NN, DIMV, D0);

    pool_div<<<(GG * OUTW + TB - 1) / TB, TB>>>(pool, cnt);
}

// round 3
// speedup vs baseline: 1.6804x; 1.0676x over previous
#include <cuda_runtime.h>
#include <cuda_bf16.h>
#include <cstdint>

#define NN   50000
#define EE   800000
#define FIN  128
#define D0   256
#define DIMV 64
#define GG   256
#define OUTW 320   // D0 + DIMV

// ---------------- scratch (device globals; no allocation) ----------------
__device__ float g_q[NN * D0];
__device__ float g_k[NN * D0];
__device__ float g_v[NN * D0];
__device__ float g_o[NN * D0];        // skip, then combined pre-BN value
__device__ float g_agg[NN * D0];      // unnormalized attention aggregation
__device__ float g_h[NN * D0];        // normalized layer-0 output (layer-1 input)
__device__ float g_s[NN];             // softmax denominators
__device__ float g_stats[2 * D0];
__device__ float g_cnt[GG];
__device__ float g_Wp0[FIN * 4 * D0];
__device__ float g_bp0[4 * D0];
__device__ float g_Wp1[D0 * 4 * DIMV];
__device__ float g_bp1[4 * DIMV];

// ---------------- helpers ----------------
__device__ __forceinline__ void red_add_v4(float* ptr, float4 v) {
    asm volatile("red.global.add.v4.f32 [%0], {%1,%2,%3,%4};"
                 :: "l"(ptr), "f"(v.x), "f"(v.y), "f"(v.z), "f"(v.w) : "memory");
}
__device__ __forceinline__ float to_tf32(float x) {
    float r;
    asm("cvt.rna.tf32.f32 %0, %1;" : "=f"(r) : "f"(x));
    return r;
}
__device__ __forceinline__ void mma_tf32(float& c0, float& c1, float& c2, float& c3,
                                         uint32_t a0, uint32_t a1, uint32_t a2, uint32_t a3,
                                         uint32_t b0, uint32_t b1) {
    asm volatile("mma.sync.aligned.m16n8k8.row.col.f32.tf32.tf32.f32 "
                 "{%0,%1,%2,%3}, {%4,%5,%6,%7}, {%8,%9}, {%0,%1,%2,%3};"
                 : "+f"(c0), "+f"(c1), "+f"(c2), "+f"(c3)
                 : "r"(a0), "r"(a1), "r"(a2), "r"(a3), "r"(b0), "r"(b1));
}

// ---------------- init / pack kernels ----------------
__global__ void init_global(float* pool, float* cnt) {
    int i = blockIdx.x * blockDim.x + threadIdx.x;
    if (i < GG * OUTW) pool[i] = 0.f;
    if (i < GG) cnt[i] = 0.f;
}
__global__ void init_layer(float* s, float* stats, float4* agg, int aggq) {
    int i = blockIdx.x * blockDim.x + threadIdx.x;
    if (i < NN) s[i] = 0.f;
    if (i < 2 * D0) stats[i] = 0.f;
    for (int j = i; j < aggq; j += gridDim.x * blockDim.x)
        agg[j] = make_float4(0.f, 0.f, 0.f, 0.f);
}
__global__ void count_kernel(const int* __restrict__ batch, float* cnt) {
    int i = blockIdx.x * blockDim.x + threadIdx.x;
    if (i < NN) atomicAdd(&cnt[batch[i]], 1.f);
}
__global__ void pack_w(const float* __restrict__ W0, const float* __restrict__ W1,
                       const float* __restrict__ W2, const float* __restrict__ W3,
                       const float* __restrict__ b0, const float* __restrict__ b1,
                       const float* __restrict__ b2, const float* __restrict__ b3,
                       float* __restrict__ Wp, float* __restrict__ bp, int K, int D) {
    int Nc = 4 * D;
    int i = blockIdx.x * blockDim.x + threadIdx.x;
    if (i < K * Nc) {
        int k = i / Nc, c = i % Nc;
        int sel = c / D, cc = c % D;
        const float* W = sel == 0 ? W0 : sel == 1 ? W1 : sel == 2 ? W2 : W3;
        Wp[i] = W[k * D + cc];
    }
    if (i < Nc) {
        int sel = i / D, cc = i % D;
        const float* b = sel == 0 ? b0 : sel == 1 ? b1 : sel == 2 ? b2 : b3;
        bp[i] = b[cc];
    }
}

// ---------------- TF32 tensor-core GEMM --------------------------------------
// C[M, 4D] = A[M,K] @ Wp[K,4D] + bp, demuxed into 4 output buffers of width D.
// 128x128 block tile, BK=16, 256 threads = 8 warps in 2x4; warp tile 64x32.
#define BM 128
#define BN 128
#define BK 16
#define ASTR 20    // A smem row stride (floats) - bank-conflict-free for frag loads
#define BSTR 136   // B smem row stride

__global__ __launch_bounds__(256, 2)
void mma_gemm4(const float* __restrict__ A, const float* __restrict__ Wp,
               const float* __restrict__ bp,
               float* __restrict__ O0, float* __restrict__ O1,
               float* __restrict__ O2, float* __restrict__ O3,
               int M, int K, int D) {
    const int Nc = 4 * D;
    __shared__ float As[BM][ASTR];
    __shared__ float Bs[BK][BSTR];

    int t = threadIdx.x;
    int lane = t & 31;
    int warp = t >> 5;
    int wm = warp >> 2;          // 0..1
    int wn = warp & 3;           // 0..3
    int g = lane >> 2;           // 0..7
    int t4 = lane & 3;           // 0..3
    int row0 = blockIdx.y * BM;
    int col0 = blockIdx.x * BN;

    float acc[4][4][4] = {};     // [mtile][ntile][frag]

    // global load mapping
    int lar = t >> 1;            // A: row 0..127
    int lak = (t & 1) * 8;       // A: k offset 0 or 8
    int lbk = t >> 4;            // B: k row 0..15
    int lbc = (t & 15) * 8;      // B: col offset 0..120

    for (int k0 = 0; k0 < K; k0 += BK) {
        // A tile: 128x16
        {
            int gr = row0 + lar;
            float4 v0, v1;
            if (gr < M) {
                v0 = *(const float4*)&A[gr * K + k0 + lak];
                v1 = *(const float4*)&A[gr * K + k0 + lak + 4];
            } else {
                v0 = make_float4(0.f, 0.f, 0.f, 0.f);
                v1 = v0;
            }
            As[lar][lak + 0] = to_tf32(v0.x); As[lar][lak + 1] = to_tf32(v0.y);
            As[lar][lak + 2] = to_tf32(v0.z); As[lar][lak + 3] = to_tf32(v0.w);
            As[lar][lak + 4] = to_tf32(v1.x); As[lar][lak + 5] = to_tf32(v1.y);
            As[lar][lak + 6] = to_tf32(v1.z); As[lar][lak + 7] = to_tf32(v1.w);
        }
        // B tile: 16x128
        {
            const float* src = &Wp[(k0 + lbk) * Nc + col0 + lbc];
            float4 v0 = *(const float4*)&src[0];
            float4 v1 = *(const float4*)&src[4];
            Bs[lbk][lbc + 0] = to_tf32(v0.x); Bs[lbk][lbc + 1] = to_tf32(v0.y);
            Bs[lbk][lbc + 2] = to_tf32(v0.z); Bs[lbk][lbc + 3] = to_tf32(v0.w);
            Bs[lbk][lbc + 4] = to_tf32(v1.x); Bs[lbk][lbc + 5] = to_tf32(v1.y);
            Bs[lbk][lbc + 6] = to_tf32(v1.z); Bs[lbk][lbc + 7] = to_tf32(v1.w);
        }
        __syncthreads();

        #pragma unroll
        for (int ks = 0; ks < 2; ks++) {
            int kk = ks * 8;
            uint32_t af[4][4], bf[4][2];
            #pragma unroll
            for (int mt = 0; mt < 4; mt++) {
                int rb = wm * 64 + mt * 16;
                af[mt][0] = __float_as_uint(As[rb + g][kk + t4]);
                af[mt][1] = __float_as_uint(As[rb + g + 8][kk + t4]);
                af[mt][2] = __float_as_uint(As[rb + g][kk + t4 + 4]);
                af[mt][3] = __float_as_uint(As[rb + g + 8][kk + t4 + 4]);
            }
            #pragma unroll
            for (int nt = 0; nt < 4; nt++) {
                int cb = wn * 32 + nt * 8;
                bf[nt][0] = __float_as_uint(Bs[kk + t4][cb + g]);
                bf[nt][1] = __float_as_uint(Bs[kk + t4 + 4][cb + g]);
            }
            #pragma unroll
            for (int mt = 0; mt < 4; mt++)
                #pragma unroll
                for (int nt = 0; nt < 4; nt++)
                    mma_tf32(acc[mt][nt][0], acc[mt][nt][1], acc[mt][nt][2], acc[mt][nt][3],
                             af[mt][0], af[mt][1], af[mt][2], af[mt][3],
                             bf[nt][0], bf[nt][1]);
        }
        __syncthreads();
    }

    // epilogue: demux by column group
    #pragma unroll
    for (int nt = 0; nt < 4; nt++) {
        int cg = col0 + wn * 32 + nt * 8;     // global col base of this n-tile
        int sel = cg / D;
        int cc = cg % D;
        float* O = sel == 0 ? O0 : sel == 1 ? O1 : sel == 2 ? O2 : O3;
        int c0 = cc + 2 * t4;
        float2 bias = *(const float2*)&bp[cg + 2 * t4];
        #pragma unroll
        for (int mt = 0; mt < 4; mt++) {
            int r0 = row0 + wm * 64 + mt * 16 + g;
            if (r0 < M) {
                float2 ov = make_float2(acc[mt][nt][0] + bias.x, acc[mt][nt][1] + bias.y);
                *(float2*)&O[r0 * D + c0] = ov;
            }
            if (r0 + 8 < M) {
                float2 ov = make_float2(acc[mt][nt][2] + bias.x, acc[mt][nt][3] + bias.y);
                *(float2*)&O[(r0 + 8) * D + c0] = ov;
            }
        }
    }
}

// ---------------- fused edge pass --------------------------------------------
// GROUP lanes cooperate on one edge; D = GROUP*4*NIT.
// Computes p = exp(q[dst]·(k[src]+a·We)·scale), accumulates s[dst] += p and
// agg[dst] += p·(v[src]+a·We)  (normalization by s deferred to BN pass).
template <int GROUP, int NIT>
__global__ void edge_fused(const float* __restrict__ q, const float* __restrict__ k,
                           const float* __restrict__ v,
                           const int* __restrict__ ei, const float* __restrict__ ea,
                           const float* __restrict__ We,
                           float* __restrict__ s, float* __restrict__ agg, float scale) {
    const int D = GROUP * 4 * NIT;
    int gt = blockIdx.x * blockDim.x + threadIdx.x;
    int e = gt / GROUP;
    int sl = gt % GROUP;
    if (e >= EE) return;
    int src = ei[e];
    int dst = ei[EE + e];
    float a = ea[e];
    float sum = 0.f;
    float4 kv[NIT], wv[NIT];
    #pragma unroll
    for (int it = 0; it < NIT; it++) {
        int f = (it * GROUP + sl) * 4;
        float4 qv = *(const float4*)&q[dst * D + f];
        kv[it] = *(const float4*)&k[src * D + f];
        wv[it] = *(const float4*)&We[f];
        sum += qv.x * fmaf(a, wv[it].x, kv[it].x) + qv.y * fmaf(a, wv[it].y, kv[it].y)
             + qv.z * fmaf(a, wv[it].z, kv[it].z) + qv.w * fmaf(a, wv[it].w, kv[it].w);
    }
    #pragma unroll
    for (int off = GROUP / 2; off > 0; off >>= 1)
        sum += __shfl_xor_sync(0xffffffffu, sum, off);
    float p = expf(sum * scale);
    if (sl == 0) atomicAdd(&s[dst], p);
    #pragma unroll
    for (int it = 0; it < NIT; it++) {
        int f = (it * GROUP + sl) * 4;
        float4 vv = *(const float4*)&v[src * D + f];
        float4 msg;
        msg.x = fmaf(a, wv[it].x, vv.x) * p;
        msg.y = fmaf(a, wv[it].y, vv.y) * p;
        msg.z = fmaf(a, wv[it].z, vv.z) * p;
        msg.w = fmaf(a, wv[it].w, vv.w) * p;
        red_add_v4(&agg[dst * D + f], msg);
    }
}

// ---------------- batch norm -------------------------------------------------
// Combines o = skip + agg/s (write-back), accumulates per-column stats.
__global__ void bn_stats(float* __restrict__ O, const float* __restrict__ agg,
                         const float* __restrict__ s, float* __restrict__ stats,
                         int Nrows, int D) {
    int c = threadIdx.x;  // blockDim.x == D
    float su = 0.f, sq = 0.f;
    for (int r = blockIdx.x; r < Nrows; r += gridDim.x) {
        float inv = 1.f / (s[r] + 1e-16f);
        float val = O[r * D + c] + agg[r * D + c] * inv;
        O[r * D + c] = val;
        su += val;
        sq += val * val;
    }
    atomicAdd(&stats[c], su);
    atomicAdd(&stats[D + c], sq);
}

__global__ void bn_finalize(float* stats, int Nrows, int D) {
    int c = threadIdx.x;
    if (c >= D) return;
    float mu = stats[c] / (float)Nrows;
    float var = stats[D + c] / (float)Nrows - mu * mu;
    stats[c] = mu;
    stats[D + c] = rsqrtf(var + 1e-5f);
}

__global__ void bn_apply(const float* __restrict__ X, const float* __restrict__ stats,
                         const float* __restrict__ gamma, const float* __restrict__ beta,
                         float* __restrict__ h, float* __restrict__ xs,
                         float* __restrict__ pool, const int* __restrict__ batch,
                         int Nrows, int D, int col_off) {
    int idx = blockIdx.x * blockDim.x + threadIdx.x;
    int Dq = D >> 2;
    if (idx >= Nrows * Dq) return;
    int r = idx / Dq, c4 = (idx % Dq) * 4;
    float4 xv = *(const float4*)&X[r * D + c4];
    float4 mu = *(const float4*)&stats[c4];
    float4 rs = *(const float4*)&stats[D + c4];
    float4 gm = *(const float4*)&gamma[c4];
    float4 bt = *(const float4*)&beta[c4];
    float4 val;
    val.x = gm.x * (xv.x - mu.x) * rs.x + bt.x;
    val.y = gm.y * (xv.y - mu.y) * rs.y + bt.y;
    val.z = gm.z * (xv.z - mu.z) * rs.z + bt.z;
    val.w = gm.w * (xv.w - mu.w) * rs.w + bt.w;
    if (h) *(float4*)&h[r * D + c4] = val;
    *(float4*)&xs[r * OUTW + col_off + c4] = val;
    red_add_v4(&pool[batch[r] * OUTW + col_off + c4], val);
}

__global__ void pool_div(float* pool, const float* __restrict__ cnt) {
    int i = blockIdx.x * blockDim.x + threadIdx.x;
    if (i >= GG * OUTW) return;
    pool[i] /= fmaxf(cnt[i / OUTW], 1.f);
}

// ---------------- launch -----------------------------------------------------
extern "C" void kernel_launch(void* const* d_in, const int* in_sizes, int n_in,
                              void* d_out, int out_size) {
    const float* x     = (const float*)d_in[0];
    const int*   ei    = (const int*)  d_in[1];
    const float* ea    = (const float*)d_in[2];
    const int*   batch = (const int*)  d_in[3];
    const float* Wq0 = (const float*)d_in[4];  const float* bq0 = (const float*)d_in[5];
    const float* Wk0 = (const float*)d_in[6];  const float* bk0 = (const float*)d_in[7];
    const float* Wv0 = (const float*)d_in[8];  const float* bv0 = (const float*)d_in[9];
    const float* We0 = (const float*)d_in[10];
    const float* Ws0 = (const float*)d_in[11]; const float* bs0 = (const float*)d_in[12];
    const float* gamma0 = (const float*)d_in[13]; const float* beta0 = (const float*)d_in[14];
    const float* Wq1 = (const float*)d_in[15]; const float* bq1 = (const float*)d_in[16];
    const float* Wk1 = (const float*)d_in[17]; const float* bk1 = (const float*)d_in[18];
    const float* Wv1 = (const float*)d_in[19]; const float* bv1 = (const float*)d_in[20];
    const float* We1 = (const float*)d_in[21];
    const float* Ws1 = (const float*)d_in[22]; const float* bs1 = (const float*)d_in[23];
    const float* gamma1 = (const float*)d_in[24]; const float* beta1 = (const float*)d_in[25];

    float* out  = (float*)d_out;
    float* pool = out;               // [G, 320]
    float* xs   = out + GG * OUTW;   // [N, 320]

    float *q, *k, *v, *o, *agg, *h, *s, *stats, *cnt, *Wp0, *bp0, *Wp1, *bp1;
    cudaGetSymbolAddress((void**)&q, g_q);
    cudaGetSymbolAddress((void**)&k, g_k);
    cudaGetSymbolAddress((void**)&v, g_v);
    cudaGetSymbolAddress((void**)&o, g_o);
    cudaGetSymbolAddress((void**)&agg, g_agg);
    cudaGetSymbolAddress((void**)&h, g_h);
    cudaGetSymbolAddress((void**)&s, g_s);
    cudaGetSymbolAddress((void**)&stats, g_stats);
    cudaGetSymbolAddress((void**)&cnt, g_cnt);
    cudaGetSymbolAddress((void**)&Wp0, g_Wp0);
    cudaGetSymbolAddress((void**)&bp0, g_bp0);
    cudaGetSymbolAddress((void**)&Wp1, g_Wp1);
    cudaGetSymbolAddress((void**)&bp1, g_bp1);

    const int TB = 256;
    int nb_nodes = (NN + TB - 1) / TB;

    init_global<<<(GG * OUTW + TB - 1) / TB, TB>>>(pool, cnt);
    init_layer<<<nb_nodes, TB>>>(s, stats, (float4*)agg, NN * D0 / 4);
    count_kernel<<<nb_nodes, TB>>>(batch, cnt);
    pack_w<<<(FIN * 4 * D0 + TB - 1) / TB, TB>>>(Wq0, Wk0, Wv0, Ws0, bq0, bk0, bv0, bs0,
                                                 Wp0, bp0, FIN, D0);
    pack_w<<<(D0 * 4 * DIMV + TB - 1) / TB, TB>>>(Wq1, Wk1, Wv1, Ws1, bq1, bk1, bv1, bs1,
                                                  Wp1, bp1, D0, DIMV);

    // ---------- layer 0 ----------
    dim3 g0(4 * D0 / BN, (NN + BM - 1) / BM);
    mma_gemm4<<<g0, 256>>>(x, Wp0, bp0, q, k, v, o, NN, FIN, D0);  // skip -> o

    edge_fused<32, 2><<<(EE * 32 + TB - 1) / TB, TB>>>(q, k, v, ei, ea, We0, s, agg,
                                                       1.f / 16.f);

    bn_stats<<<256, D0>>>(o, agg, s, stats, NN, D0);
    bn_finalize<<<1, D0>>>(stats, NN, D0);
    bn_apply<<<(NN * D0 / 4 + TB - 1) / TB, TB>>>(o, stats, gamma0, beta0, h, xs, pool,
                                                  batch, NN, D0, 0);

    // ---------- layer 1 ----------
    init_layer<<<nb_nodes, TB>>>(s, stats, (float4*)agg, NN * DIMV / 4);

    dim3 g1(4 * DIMV / BN, (NN + BM - 1) / BM);
    mma_gemm4<<<g1, 256>>>(h, Wp1, bp1, q, k, v, o, NN, D0, DIMV);

    edge_fused<16, 1><<<(EE * 16 + TB - 1) / TB, TB>>>(q, k, v, ei, ea, We1, s, agg,
                                                       1.f / 8.f);

    bn_stats<<<256, DIMV>>>(o, agg, s, stats, NN, DIMV);
    bn_finalize<<<1, DIMV>>>(stats, NN, DIMV);
    bn_apply<<<(NN * DIMV / 4 + TB - 1) / TB, TB>>>(o, stats, gamma1, beta1, nullptr, xs,
                                                    pool, batch, NN, DIMV, D0);

    pool_div<<<(GG * OUTW + TB - 1) / TB, TB>>>(pool, cnt);
}

// round 4
// speedup vs baseline: 2.5238x; 1.5019x over previous
#include <cuda_runtime.h>
#include <cuda_bf16.h>
#include <cstdint>

#define NN   50000
#define EE   800000
#define FIN  128
#define D0   256
#define DIMV 64
#define GG   256
#define OUTW 320   // D0 + DIMV

// ---------------- scratch (device globals; no allocation) ----------------
__device__ float g_q[NN * D0];
__device__ float g_k[NN * D0];
__device__ float g_v[NN * D0];
__device__ float g_o[NN * D0];        // skip, then combined pre-BN value
__device__ int   g_deg[NN];           // degree, then CSR cursor, then degree
__device__ int   g_offs[NN];          // CSR row offsets
__device__ int   g_csrc[EE];          // CSR: source node per slot
__device__ float g_ca[EE];            // CSR: edge attr per slot
__device__ float g_statsA[2 * D0];
__device__ float g_statsB[2 * DIMV];
__device__ float g_cnt[GG];
__device__ float g_Wp0[FIN * 4 * D0];
__device__ float g_bp0[4 * D0];
__device__ float g_Wp1[D0 * 4 * DIMV];
__device__ float g_bp1[4 * DIMV];

// ---------------- helpers ----------------
__device__ __forceinline__ void red_add_v4(float* ptr, float4 v) {
    asm volatile("red.global.add.v4.f32 [%0], {%1,%2,%3,%4};"
                 :: "l"(ptr), "f"(v.x), "f"(v.y), "f"(v.z), "f"(v.w) : "memory");
}
__device__ __forceinline__ float to_tf32(float x) {
    float r;
    asm("cvt.rna.tf32.f32 %0, %1;" : "=f"(r) : "f"(x));
    return r;
}
__device__ __forceinline__ void mma_tf32(float& c0, float& c1, float& c2, float& c3,
                                         uint32_t a0, uint32_t a1, uint32_t a2, uint32_t a3,
                                         uint32_t b0, uint32_t b1) {
    asm volatile("mma.sync.aligned.m16n8k8.row.col.f32.tf32.tf32.f32 "
                 "{%0,%1,%2,%3}, {%4,%5,%6,%7}, {%8,%9}, {%0,%1,%2,%3};"
                 : "+f"(c0), "+f"(c1), "+f"(c2), "+f"(c3)
                 : "r"(a0), "r"(a1), "r"(a2), "r"(a3), "r"(b0), "r"(b1));
}

// ---------------- prep: all zeroing + weight packing in ONE launch -----------
__global__ void prep(float* pool, float* cnt, int* deg, float* statsA, float* statsB,
                     const float* __restrict__ Wq0, const float* __restrict__ Wk0,
                     const float* __restrict__ Wv0, const float* __restrict__ Ws0,
                     const float* __restrict__ bq0, const float* __restrict__ bk0,
                     const float* __restrict__ bv0, const float* __restrict__ bs0,
                     const float* __restrict__ Wq1, const float* __restrict__ Wk1,
                     const float* __restrict__ Wv1, const float* __restrict__ Ws1,
                     const float* __restrict__ bq1, const float* __restrict__ bk1,
                     const float* __restrict__ bv1, const float* __restrict__ bs1,
                     float* Wp0, float* bp0, float* Wp1, float* bp1) {
    int gs = gridDim.x * blockDim.x;
    int i0 = blockIdx.x * blockDim.x + threadIdx.x;
    for (int i = i0; i < GG * OUTW; i += gs) pool[i] = 0.f;
    for (int i = i0; i < GG; i += gs) cnt[i] = 0.f;
    for (int i = i0; i < NN; i += gs) deg[i] = 0;
    for (int i = i0; i < 2 * D0; i += gs) statsA[i] = 0.f;
    for (int i = i0; i < 2 * DIMV; i += gs) statsB[i] = 0.f;
    // pack layer-0 weights [FIN, 4*D0]
    for (int i = i0; i < FIN * 4 * D0; i += gs) {
        int kk = i / (4 * D0), c = i % (4 * D0);
        int sel = c / D0, cc = c % D0;
        const float* W = sel == 0 ? Wq0 : sel == 1 ? Wk0 : sel == 2 ? Wv0 : Ws0;
        Wp0[i] = W[kk * D0 + cc];
    }
    for (int i = i0; i < 4 * D0; i += gs) {
        int sel = i / D0, cc = i % D0;
        const float* b = sel == 0 ? bq0 : sel == 1 ? bk0 : sel == 2 ? bv0 : bs0;
        bp0[i] = b[cc];
    }
    // pack layer-1 weights [D0, 4*DIMV]
    for (int i = i0; i < D0 * 4 * DIMV; i += gs) {
        int kk = i / (4 * DIMV), c = i % (4 * DIMV);
        int sel = c / DIMV, cc = c % DIMV;
        const float* W = sel == 0 ? Wq1 : sel == 1 ? Wk1 : sel == 2 ? Wv1 : Ws1;
        Wp1[i] = W[kk * DIMV + cc];
    }
    for (int i = i0; i < 4 * DIMV; i += gs) {
        int sel = i / DIMV, cc = i % DIMV;
        const float* b = sel == 0 ? bq1 : sel == 1 ? bk1 : sel == 2 ? bv1 : bs1;
        bp1[i] = b[cc];
    }
}

// ---------------- CSR build --------------------------------------------------
__global__ void hist_count(const int* __restrict__ ei, int* deg,
                           const int* __restrict__ batch, float* cnt) {
    int i = blockIdx.x * blockDim.x + threadIdx.x;
    if (i < EE) atomicAdd(&deg[ei[EE + i]], 1);
    if (i < NN) atomicAdd(&cnt[batch[i]], 1.f);
}

__global__ void scan_kernel(int* deg, int* offs) {   // 1 block, 1024 threads
    __shared__ int ps[1024];
    int t = threadIdx.x;
    const int CH = (NN + 1023) / 1024;
    int base = t * CH;
    int sum = 0;
    for (int i = 0; i < CH; i++) {
        int idx = base + i;
        if (idx < NN) sum += deg[idx];
    }
    ps[t] = sum;
    __syncthreads();
    for (int off = 1; off < 1024; off <<= 1) {
        int v = (t >= off) ? ps[t - off] : 0;
        __syncthreads();
        ps[t] += v;
        __syncthreads();
    }
    int run = (t > 0) ? ps[t - 1] : 0;
    for (int i = 0; i < CH; i++) {
        int idx = base + i;
        if (idx < NN) {
            offs[idx] = run;
            run += deg[idx];
            deg[idx] = 0;   // reset as fill cursor
        }
    }
}

__global__ void fill_csr(const int* __restrict__ ei, const float* __restrict__ ea,
                         const int* __restrict__ offs, int* deg,
                         int* csrc, float* ca) {
    int e = blockIdx.x * blockDim.x + threadIdx.x;
    if (e >= EE) return;
    int dst = ei[EE + e];
    int slot = offs[dst] + atomicAdd(&deg[dst], 1);
    csrc[slot] = ei[e];
    ca[slot] = ea[e];
}

// ---------------- TF32 tensor-core GEMM --------------------------------------
#define BM 128
#define BN 128
#define BK 16
#define ASTR 20
#define BSTR 136

__global__ __launch_bounds__(256, 2)
void mma_gemm4(const float* __restrict__ A, const float* __restrict__ Wp,
               const float* __restrict__ bp,
               float* __restrict__ O0, float* __restrict__ O1,
               float* __restrict__ O2, float* __restrict__ O3,
               int M, int K, int lda, int D) {
    const int Nc = 4 * D;
    __shared__ float As[BM][ASTR];
    __shared__ float Bs[BK][BSTR];

    int t = threadIdx.x;
    int lane = t & 31;
    int warp = t >> 5;
    int wm = warp >> 2;
    int wn = warp & 3;
    int g = lane >> 2;
    int t4 = lane & 3;
    int row0 = blockIdx.y * BM;
    int col0 = blockIdx.x * BN;

    float acc[4][4][4] = {};

    int lar = t >> 1;
    int lak = (t & 1) * 8;
    int lbk = t >> 4;
    int lbc = (t & 15) * 8;

    for (int k0 = 0; k0 < K; k0 += BK) {
        {
            int gr = row0 + lar;
            float4 v0, v1;
            if (gr < M) {
                v0 = *(const float4*)&A[gr * lda + k0 + lak];
                v1 = *(const float4*)&A[gr * lda + k0 + lak + 4];
            } else {
                v0 = make_float4(0.f, 0.f, 0.f, 0.f);
                v1 = v0;
            }
            As[lar][lak + 0] = to_tf32(v0.x); As[lar][lak + 1] = to_tf32(v0.y);
            As[lar][lak + 2] = to_tf32(v0.z); As[lar][lak + 3] = to_tf32(v0.w);
            As[lar][lak + 4] = to_tf32(v1.x); As[lar][lak + 5] = to_tf32(v1.y);
            As[lar][lak + 6] = to_tf32(v1.z); As[lar][lak + 7] = to_tf32(v1.w);
        }
        {
            const float* src = &Wp[(k0 + lbk) * Nc + col0 + lbc];
            float4 v0 = *(const float4*)&src[0];
            float4 v1 = *(const float4*)&src[4];
            Bs[lbk][lbc + 0] = to_tf32(v0.x); Bs[lbk][lbc + 1] = to_tf32(v0.y);
            Bs[lbk][lbc + 2] = to_tf32(v0.z); Bs[lbk][lbc + 3] = to_tf32(v0.w);
            Bs[lbk][lbc + 4] = to_tf32(v1.x); Bs[lbk][lbc + 5] = to_tf32(v1.y);
            Bs[lbk][lbc + 6] = to_tf32(v1.z); Bs[lbk][lbc + 7] = to_tf32(v1.w);
        }
        __syncthreads();

        #pragma unroll
        for (int ks = 0; ks < 2; ks++) {
            int kk = ks * 8;
            uint32_t af[4][4], bf[4][2];
            #pragma unroll
            for (int mt = 0; mt < 4; mt++) {
                int rb = wm * 64 + mt * 16;
                af[mt][0] = __float_as_uint(As[rb + g][kk + t4]);
                af[mt][1] = __float_as_uint(As[rb + g + 8][kk + t4]);
                af[mt][2] = __float_as_uint(As[rb + g][kk + t4 + 4]);
                af[mt][3] = __float_as_uint(As[rb + g + 8][kk + t4 + 4]);
            }
            #pragma unroll
            for (int nt = 0; nt < 4; nt++) {
                int cb = wn * 32 + nt * 8;
                bf[nt][0] = __float_as_uint(Bs[kk + t4][cb + g]);
                bf[nt][1] = __float_as_uint(Bs[kk + t4 + 4][cb + g]);
            }
            #pragma unroll
            for (int mt = 0; mt < 4; mt++)
                #pragma unroll
                for (int nt = 0; nt < 4; nt++)
                    mma_tf32(acc[mt][nt][0], acc[mt][nt][1], acc[mt][nt][2], acc[mt][nt][3],
                             af[mt][0], af[mt][1], af[mt][2], af[mt][3],
                             bf[nt][0], bf[nt][1]);
        }
        __syncthreads();
    }

    #pragma unroll
    for (int nt = 0; nt < 4; nt++) {
        int cg = col0 + wn * 32 + nt * 8;
        int sel = cg / D;
        int cc = cg % D;
        float* O = sel == 0 ? O0 : sel == 1 ? O1 : sel == 2 ? O2 : O3;
        int c0 = cc + 2 * t4;
        float2 bias = *(const float2*)&bp[cg + 2 * t4];
        #pragma unroll
        for (int mt = 0; mt < 4; mt++) {
            int r0 = row0 + wm * 64 + mt * 16 + g;
            if (r0 < M) {
                float2 ov = make_float2(acc[mt][nt][0] + bias.x, acc[mt][nt][1] + bias.y);
                *(float2*)&O[r0 * D + c0] = ov;
            }
            if (r0 + 8 < M) {
                float2 ov = make_float2(acc[mt][nt][2] + bias.x, acc[mt][nt][3] + bias.y);
                *(float2*)&O[(r0 + 8) * D + c0] = ov;
            }
        }
    }
}

// ---------------- node aggregation (warp per node, CSR gather) ---------------
// Computes per-node softmax attention aggregation in registers, combines with
// skip (already in o), writes o, and accumulates BN column stats.
template <int D>
__global__ __launch_bounds__(256)
void node_agg(const float* __restrict__ q, const float* __restrict__ k,
              const float* __restrict__ v, float* __restrict__ o,
              const int* __restrict__ offs, const int* __restrict__ deg,
              const int* __restrict__ csrc, const float* __restrict__ ca,
              const float* __restrict__ We, float* __restrict__ stats, float scale) {
    constexpr int C = D / 32;   // floats per lane (8 for D0, 2 for DIMV)
    __shared__ float ssu[D], ssq[D];
    int t = threadIdx.x;
    int lane = t & 31;
    for (int i = t; i < D; i += 256) { ssu[i] = 0.f; ssq[i] = 0.f; }
    __syncthreads();

    // column map: D==256 -> lane*4+{0..3}, 128+lane*4+{0..3}; D==64 -> lane*2+{0,1}
    int col[C];
    if constexpr (D == 256) {
        #pragma unroll
        for (int i = 0; i < 4; i++) { col[i] = lane * 4 + i; col[4 + i] = 128 + lane * 4 + i; }
    } else {
        #pragma unroll
        for (int i = 0; i < C; i++) col[i] = lane * C + i;
    }

    float we[C];
    #pragma unroll
    for (int i = 0; i < C; i++) we[i] = We[col[i]];

    float su[C] = {}, sq[C] = {};

    int wg = blockIdx.x * 8 + (t >> 5);
    int tw = gridDim.x * 8;

    for (int n = wg; n < NN; n += tw) {
        float qr[C], acc[C] = {};
        float s = 0.f;
        if constexpr (D == 256) {
            float4 a0 = *(const float4*)&q[n * D + lane * 4];
            float4 a1 = *(const float4*)&q[n * D + 128 + lane * 4];
            qr[0] = a0.x; qr[1] = a0.y; qr[2] = a0.z; qr[3] = a0.w;
            qr[4] = a1.x; qr[5] = a1.y; qr[6] = a1.z; qr[7] = a1.w;
        } else {
            float2 a0 = *(const float2*)&q[n * D + lane * 2];
            qr[0] = a0.x; qr[1] = a0.y;
        }
        int jb = offs[n], je = jb + deg[n];
        for (int j = jb; j < je; j++) {
            int src = __ldg(&csrc[j]);
            float a = __ldg(&ca[j]);
            float kr[C], vr[C];
            if constexpr (D == 256) {
                float4 k0 = *(const float4*)&k[src * D + lane * 4];
                float4 k1 = *(const float4*)&k[src * D + 128 + lane * 4];
                float4 v0 = *(const float4*)&v[src * D + lane * 4];
                float4 v1 = *(const float4*)&v[src * D + 128 + lane * 4];
                kr[0] = k0.x; kr[1] = k0.y; kr[2] = k0.z; kr[3] = k0.w;
                kr[4] = k1.x; kr[5] = k1.y; kr[6] = k1.z; kr[7] = k1.w;
                vr[0] = v0.x; vr[1] = v0.y; vr[2] = v0.z; vr[3] = v0.w;
                vr[4] = v1.x; vr[5] = v1.y; vr[6] = v1.z; vr[7] = v1.w;
            } else {
                float2 k0 = *(const float2*)&k[src * D + lane * 2];
                float2 v0 = *(const float2*)&v[src * D + lane * 2];
                kr[0] = k0.x; kr[1] = k0.y;
                vr[0] = v0.x; vr[1] = v0.y;
            }
            float part = 0.f;
            #pragma unroll
            for (int i = 0; i < C; i++) part += qr[i] * fmaf(a, we[i], kr[i]);
            #pragma unroll
            for (int off = 16; off > 0; off >>= 1)
                part += __shfl_xor_sync(0xffffffffu, part, off);
            float p = expf(part * scale);
            s += p;
            #pragma unroll
            for (int i = 0; i < C; i++) acc[i] = fmaf(p, fmaf(a, we[i], vr[i]), acc[i]);
        }
        float inv = 1.f / (s + 1e-16f);
        float val[C];
        if constexpr (D == 256) {
            float4 s0 = *(const float4*)&o[n * D + lane * 4];
            float4 s1 = *(const float4*)&o[n * D + 128 + lane * 4];
            val[0] = s0.x + acc[0] * inv; val[1] = s0.y + acc[1] * inv;
            val[2] = s0.z + acc[2] * inv; val[3] = s0.w + acc[3] * inv;
            val[4] = s1.x + acc[4] * inv; val[5] = s1.y + acc[5] * inv;
            val[6] = s1.z + acc[6] * inv; val[7] = s1.w + acc[7] * inv;
            *(float4*)&o[n * D + lane * 4] = make_float4(val[0], val[1], val[2], val[3]);
            *(float4*)&o[n * D + 128 + lane * 4] = make_float4(val[4], val[5], val[6], val[7]);
        } else {
            float2 s0 = *(const float2*)&o[n * D + lane * 2];
            val[0] = s0.x + acc[0] * inv; val[1] = s0.y + acc[1] * inv;
            *(float2*)&o[n * D + lane * 2] = make_float2(val[0], val[1]);
        }
        #pragma unroll
        for (int i = 0; i < C; i++) { su[i] += val[i]; sq[i] += val[i] * val[i]; }
    }

    #pragma unroll
    for (int i = 0; i < C; i++) {
        atomicAdd(&ssu[col[i]], su[i]);
        atomicAdd(&ssq[col[i]], sq[i]);
    }
    __syncthreads();
    for (int i = t; i < D; i += 256) {
        atomicAdd(&stats[i], ssu[i]);
        atomicAdd(&stats[D + i], ssq[i]);
    }
}

// ---------------- batch norm -------------------------------------------------
__global__ void bn_finalize(float* stats, int Nrows, int D) {
    int c = threadIdx.x;
    if (c >= D) return;
    float mu = stats[c] / (float)Nrows;
    float var = stats[D + c] / (float)Nrows - mu * mu;
    stats[c] = mu;
    stats[D + c] = rsqrtf(var + 1e-5f);
}

__global__ void bn_apply(const float* __restrict__ X, const float* __restrict__ stats,
                         const float* __restrict__ gamma, const float* __restrict__ beta,
                         float* __restrict__ xs, float* __restrict__ pool,
                         const int* __restrict__ batch, int Nrows, int D, int col_off) {
    int idx = blockIdx.x * blockDim.x + threadIdx.x;
    int Dq = D >> 2;
    if (idx >= Nrows * Dq) return;
    int r = idx / Dq, c4 = (idx % Dq) * 4;
    float4 xv = *(const float4*)&X[r * D + c4];
    float4 mu = *(const float4*)&stats[c4];
    float4 rs = *(const float4*)&stats[D + c4];
    float4 gm = *(const float4*)&gamma[c4];
    float4 bt = *(const float4*)&beta[c4];
    float4 val;
    val.x = gm.x * (xv.x - mu.x) * rs.x + bt.x;
    val.y = gm.y * (xv.y - mu.y) * rs.y + bt.y;
    val.z = gm.z * (xv.z - mu.z) * rs.z + bt.z;
    val.w = gm.w * (xv.w - mu.w) * rs.w + bt.w;
    *(float4*)&xs[r * OUTW + col_off + c4] = val;
    red_add_v4(&pool[batch[r] * OUTW + col_off + c4], val);
}

__global__ void pool_div(float* pool, const float* __restrict__ cnt) {
    int i = blockIdx.x * blockDim.x + threadIdx.x;
    if (i >= GG * OUTW) return;
    pool[i] /= fmaxf(cnt[i / OUTW], 1.f);
}

// ---------------- launch -----------------------------------------------------
extern "C" void kernel_launch(void* const* d_in, const int* in_sizes, int n_in,
                              void* d_out, int out_size) {
    const float* x     = (const float*)d_in[0];
    const int*   ei    = (const int*)  d_in[1];
    const float* ea    = (const float*)d_in[2];
    const int*   batch = (const int*)  d_in[3];
    const float* Wq0 = (const float*)d_in[4];  const float* bq0 = (const float*)d_in[5];
    const float* Wk0 = (const float*)d_in[6];  const float* bk0 = (const float*)d_in[7];
    const float* Wv0 = (const float*)d_in[8];  const float* bv0 = (const float*)d_in[9];
    const float* We0 = (const float*)d_in[10];
    const float* Ws0 = (const float*)d_in[11]; const float* bs0 = (const float*)d_in[12];
    const float* gamma0 = (const float*)d_in[13]; const float* beta0 = (const float*)d_in[14];
    const float* Wq1 = (const float*)d_in[15]; const float* bq1 = (const float*)d_in[16];
    const float* Wk1 = (const float*)d_in[17]; const float* bk1 = (const float*)d_in[18];
    const float* Wv1 = (const float*)d_in[19]; const float* bv1 = (const float*)d_in[20];
    const float* We1 = (const float*)d_in[21];
    const float* Ws1 = (const float*)d_in[22]; const float* bs1 = (const float*)d_in[23];
    const float* gamma1 = (const float*)d_in[24]; const float* beta1 = (const float*)d_in[25];

    float* out  = (float*)d_out;
    float* pool = out;               // [G, 320]
    float* xs   = out + GG * OUTW;   // [N, 320]

    float *q, *k, *v, *o, *statsA, *statsB, *cnt, *Wp0, *bp0, *Wp1, *bp1, *ca;
    int *deg, *offs, *csrc;
    cudaGetSymbolAddress((void**)&q, g_q);
    cudaGetSymbolAddress((void**)&k, g_k);
    cudaGetSymbolAddress((void**)&v, g_v);
    cudaGetSymbolAddress((void**)&o, g_o);
    cudaGetSymbolAddress((void**)&deg, g_deg);
    cudaGetSymbolAddress((void**)&offs, g_offs);
    cudaGetSymbolAddress((void**)&csrc, g_csrc);
    cudaGetSymbolAddress((void**)&ca, g_ca);
    cudaGetSymbolAddress((void**)&statsA, g_statsA);
    cudaGetSymbolAddress((void**)&statsB, g_statsB);
    cudaGetSymbolAddress((void**)&cnt, g_cnt);
    cudaGetSymbolAddress((void**)&Wp0, g_Wp0);
    cudaGetSymbolAddress((void**)&bp0, g_bp0);
    cudaGetSymbolAddress((void**)&Wp1, g_Wp1);
    cudaGetSymbolAddress((void**)&bp1, g_bp1);

    const int TB = 256;

    // 1: prep (all zero-init + weight packing)
    prep<<<512, TB>>>(pool, cnt, deg, statsA, statsB,
                      Wq0, Wk0, Wv0, Ws0, bq0, bk0, bv0, bs0,
                      Wq1, Wk1, Wv1, Ws1, bq1, bk1, bv1, bs1,
                      Wp0, bp0, Wp1, bp1);
    // 2-4: CSR build
    hist_count<<<(EE + TB - 1) / TB, TB>>>(ei, deg, batch, cnt);
    scan_kernel<<<1, 1024>>>(deg, offs);
    fill_csr<<<(EE + TB - 1) / TB, TB>>>(ei, ea, offs, deg, csrc, ca);

    // 5: layer-0 GEMM (profiled slot)
    dim3 g0(4 * D0 / BN, (NN + BM - 1) / BM);
    mma_gemm4<<<g0, 256>>>(x, Wp0, bp0, q, k, v, o, NN, FIN, FIN, D0);

    // 6: layer-0 node aggregation (+BN stats)
    node_agg<D0><<<1184, 256>>>(q, k, v, o, offs, deg, csrc, ca, We0, statsA, 1.f / 16.f);

    bn_finalize<<<1, D0>>>(statsA, NN, D0);
    bn_apply<<<(NN * D0 / 4 + TB - 1) / TB, TB>>>(o, statsA, gamma0, beta0, xs, pool,
                                                  batch, NN, D0, 0);

    // layer 1 (A = xs slab, lda=OUTW)
    dim3 g1(4 * DIMV / BN, (NN + BM - 1) / BM);
    mma_gemm4<<<g1, 256>>>(xs, Wp1, bp1, q, k, v, o, NN, D0, OUTW, DIMV);

    node_agg<DIMV><<<1184, 256>>>(q, k, v, o, offs, deg, csrc, ca, We1, statsB, 1.f / 8.f);

    bn_finalize<<<1, DIMV>>>(statsB, NN, DIMV);
    bn_apply<<<(NN * DIMV / 4 + TB - 1) / TB, TB>>>(o, statsB, gamma1, beta1, xs, pool,
                                                    batch, NN, DIMV, D0);

    pool_div<<<(GG * OUTW + TB - 1) / TB, TB>>>(pool, cnt);
}

// round 5
// speedup vs baseline: 2.8303x; 1.1214x over previous
#include <cuda_runtime.h>
#include <cuda_fp16.h>
#include <cstdint>

#define NN   50000
#define EE   800000
#define FIN  128
#define D0   256
#define DIMV 64
#define GG   256
#define OUTW 320   // D0 + DIMV

// ---------------- scratch (device globals; no allocation) ----------------
__device__ float  g_q[NN * D0];
__device__ __half g_kh[NN * D0];
__device__ __half g_vh[NN * D0];
__device__ float  g_o[NN * D0];       // skip, then combined pre-BN value
__device__ int    g_deg[NN];
__device__ int    g_offs[NN];
__device__ int    g_csrc[EE];
__device__ float  g_ca[EE];
__device__ float  g_statsA[2 * D0];
__device__ float  g_statsB[2 * DIMV];
__device__ float  g_cnt[GG];
__device__ float  g_Wp0[FIN * 4 * D0];
__device__ float  g_bp0[4 * D0];
__device__ float  g_Wp1[D0 * 4 * DIMV];
__device__ float  g_bp1[4 * DIMV];

// ---------------- helpers ----------------
__device__ __forceinline__ void red_add_v4(float* ptr, float4 v) {
    asm volatile("red.global.add.v4.f32 [%0], {%1,%2,%3,%4};"
                 :: "l"(ptr), "f"(v.x), "f"(v.y), "f"(v.z), "f"(v.w) : "memory");
}
__device__ __forceinline__ float to_tf32(float x) {
    float r;
    asm("cvt.rna.tf32.f32 %0, %1;" : "=f"(r) : "f"(x));
    return r;
}
__device__ __forceinline__ void mma_tf32(float& c0, float& c1, float& c2, float& c3,
                                         uint32_t a0, uint32_t a1, uint32_t a2, uint32_t a3,
                                         uint32_t b0, uint32_t b1) {
    asm volatile("mma.sync.aligned.m16n8k8.row.col.f32.tf32.tf32.f32 "
                 "{%0,%1,%2,%3}, {%4,%5,%6,%7}, {%8,%9}, {%0,%1,%2,%3};"
                 : "+f"(c0), "+f"(c1), "+f"(c2), "+f"(c3)
                 : "r"(a0), "r"(a1), "r"(a2), "r"(a3), "r"(b0), "r"(b1));
}

// ---------------- prep: all zeroing + weight packing in ONE launch -----------
__global__ void prep(float* pool, float* cnt, int* deg, float* statsA, float* statsB,
                     const float* __restrict__ Wq0, const float* __restrict__ Wk0,
                     const float* __restrict__ Wv0, const float* __restrict__ Ws0,
                     const float* __restrict__ bq0, const float* __restrict__ bk0,
                     const float* __restrict__ bv0, const float* __restrict__ bs0,
                     const float* __restrict__ Wq1, const float* __restrict__ Wk1,
                     const float* __restrict__ Wv1, const float* __restrict__ Ws1,
                     const float* __restrict__ bq1, const float* __restrict__ bk1,
                     const float* __restrict__ bv1, const float* __restrict__ bs1,
                     float* Wp0, float* bp0, float* Wp1, float* bp1) {
    int gs = gridDim.x * blockDim.x;
    int i0 = blockIdx.x * blockDim.x + threadIdx.x;
    for (int i = i0; i < GG * OUTW; i += gs) pool[i] = 0.f;
    for (int i = i0; i < GG; i += gs) cnt[i] = 0.f;
    for (int i = i0; i < NN; i += gs) deg[i] = 0;
    for (int i = i0; i < 2 * D0; i += gs) statsA[i] = 0.f;
    for (int i = i0; i < 2 * DIMV; i += gs) statsB[i] = 0.f;
    for (int i = i0; i < FIN * 4 * D0; i += gs) {
        int kk = i / (4 * D0), c = i % (4 * D0);
        int sel = c / D0, cc = c % D0;
        const float* W = sel == 0 ? Wq0 : sel == 1 ? Wk0 : sel == 2 ? Wv0 : Ws0;
        Wp0[i] = W[kk * D0 + cc];
    }
    for (int i = i0; i < 4 * D0; i += gs) {
        int sel = i / D0, cc = i % D0;
        const float* b = sel == 0 ? bq0 : sel == 1 ? bk0 : sel == 2 ? bv0 : bs0;
        bp0[i] = b[cc];
    }
    for (int i = i0; i < D0 * 4 * DIMV; i += gs) {
        int kk = i / (4 * DIMV), c = i % (4 * DIMV);
        int sel = c / DIMV, cc = c % DIMV;
        const float* W = sel == 0 ? Wq1 : sel == 1 ? Wk1 : sel == 2 ? Wv1 : Ws1;
        Wp1[i] = W[kk * DIMV + cc];
    }
    for (int i = i0; i < 4 * DIMV; i += gs) {
        int sel = i / DIMV, cc = i % DIMV;
        const float* b = sel == 0 ? bq1 : sel == 1 ? bk1 : sel == 2 ? bv1 : bs1;
        bp1[i] = b[cc];
    }
}

// ---------------- CSR build --------------------------------------------------
__global__ void hist_count(const int* __restrict__ ei, int* deg,
                           const int* __restrict__ batch, float* cnt) {
    int i = blockIdx.x * blockDim.x + threadIdx.x;
    if (i < EE) atomicAdd(&deg[ei[EE + i]], 1);
    if (i < NN) atomicAdd(&cnt[batch[i]], 1.f);
}

__global__ void scan_kernel(int* deg, int* offs) {   // 1 block, 1024 threads
    __shared__ int ps[1024];
    int t = threadIdx.x;
    const int CH = (NN + 1023) / 1024;
    int base = t * CH;
    int sum = 0;
    for (int i = 0; i < CH; i++) {
        int idx = base + i;
        if (idx < NN) sum += deg[idx];
    }
    ps[t] = sum;
    __syncthreads();
    for (int off = 1; off < 1024; off <<= 1) {
        int v = (t >= off) ? ps[t - off] : 0;
        __syncthreads();
        ps[t] += v;
        __syncthreads();
    }
    int run = (t > 0) ? ps[t - 1] : 0;
    for (int i = 0; i < CH; i++) {
        int idx = base + i;
        if (idx < NN) {
            offs[idx] = run;
            run += deg[idx];
            deg[idx] = 0;
        }
    }
}

__global__ void fill_csr(const int* __restrict__ ei, const float* __restrict__ ea,
                         const int* __restrict__ offs, int* deg,
                         int* csrc, float* ca) {
    int e = blockIdx.x * blockDim.x + threadIdx.x;
    if (e >= EE) return;
    int dst = ei[EE + e];
    int slot = offs[dst] + atomicAdd(&deg[dst], 1);
    csrc[slot] = ei[e];
    ca[slot] = ea[e];
}

// ---------------- TF32 tensor-core GEMM --------------------------------------
// [M, 4D] = A @ Wp + bp; col groups 0/3 -> float (q, skip), 1/2 -> half (k, v).
#define BM 128
#define BN 128
#define BK 16
#define ASTR 20
#define BSTR 136

__global__ __launch_bounds__(256, 2)
void mma_gemm4(const float* __restrict__ A, const float* __restrict__ Wp,
               const float* __restrict__ bp,
               float* __restrict__ Oq, __half* __restrict__ Ok,
               __half* __restrict__ Ov, float* __restrict__ Oo,
               int M, int K, int lda, int D) {
    const int Nc = 4 * D;
    __shared__ float As[BM][ASTR];
    __shared__ float Bs[BK][BSTR];

    int t = threadIdx.x;
    int lane = t & 31;
    int warp = t >> 5;
    int wm = warp >> 2;
    int wn = warp & 3;
    int g = lane >> 2;
    int t4 = lane & 3;
    int row0 = blockIdx.y * BM;
    int col0 = blockIdx.x * BN;

    float acc[4][4][4] = {};

    int lar = t >> 1;
    int lak = (t & 1) * 8;
    int lbk = t >> 4;
    int lbc = (t & 15) * 8;

    for (int k0 = 0; k0 < K; k0 += BK) {
        {
            int gr = row0 + lar;
            float4 v0, v1;
            if (gr < M) {
                v0 = *(const float4*)&A[gr * lda + k0 + lak];
                v1 = *(const float4*)&A[gr * lda + k0 + lak + 4];
            } else {
                v0 = make_float4(0.f, 0.f, 0.f, 0.f);
                v1 = v0;
            }
            As[lar][lak + 0] = to_tf32(v0.x); As[lar][lak + 1] = to_tf32(v0.y);
            As[lar][lak + 2] = to_tf32(v0.z); As[lar][lak + 3] = to_tf32(v0.w);
            As[lar][lak + 4] = to_tf32(v1.x); As[lar][lak + 5] = to_tf32(v1.y);
            As[lar][lak + 6] = to_tf32(v1.z); As[lar][lak + 7] = to_tf32(v1.w);
        }
        {
            const float* src = &Wp[(k0 + lbk) * Nc + col0 + lbc];
            float4 v0 = *(const float4*)&src[0];
            float4 v1 = *(const float4*)&src[4];
            Bs[lbk][lbc + 0] = to_tf32(v0.x); Bs[lbk][lbc + 1] = to_tf32(v0.y);
            Bs[lbk][lbc + 2] = to_tf32(v0.z); Bs[lbk][lbc + 3] = to_tf32(v0.w);
            Bs[lbk][lbc + 4] = to_tf32(v1.x); Bs[lbk][lbc + 5] = to_tf32(v1.y);
            Bs[lbk][lbc + 6] = to_tf32(v1.z); Bs[lbk][lbc + 7] = to_tf32(v1.w);
        }
        __syncthreads();

        #pragma unroll
        for (int ks = 0; ks < 2; ks++) {
            int kk = ks * 8;
            uint32_t af[4][4], bf[4][2];
            #pragma unroll
            for (int mt = 0; mt < 4; mt++) {
                int rb = wm * 64 + mt * 16;
                af[mt][0] = __float_as_uint(As[rb + g][kk + t4]);
                af[mt][1] = __float_as_uint(As[rb + g + 8][kk + t4]);
                af[mt][2] = __float_as_uint(As[rb + g][kk + t4 + 4]);
                af[mt][3] = __float_as_uint(As[rb + g + 8][kk + t4 + 4]);
            }
            #pragma unroll
            for (int nt = 0; nt < 4; nt++) {
                int cb = wn * 32 + nt * 8;
                bf[nt][0] = __float_as_uint(Bs[kk + t4][cb + g]);
                bf[nt][1] = __float_as_uint(Bs[kk + t4 + 4][cb + g]);
            }
            #pragma unroll
            for (int mt = 0; mt < 4; mt++)
                #pragma unroll
                for (int nt = 0; nt < 4; nt++)
                    mma_tf32(acc[mt][nt][0], acc[mt][nt][1], acc[mt][nt][2], acc[mt][nt][3],
                             af[mt][0], af[mt][1], af[mt][2], af[mt][3],
                             bf[nt][0], bf[nt][1]);
        }
        __syncthreads();
    }

    #pragma unroll
    for (int nt = 0; nt < 4; nt++) {
        int cg = col0 + wn * 32 + nt * 8;
        int sel = cg / D;
        int cc = cg % D;
        int c0 = cc + 2 * t4;
        float2 bias = *(const float2*)&bp[cg + 2 * t4];
        if (sel == 1 || sel == 2) {
            __half* O = (sel == 1) ? Ok : Ov;
            #pragma unroll
            for (int mt = 0; mt < 4; mt++) {
                int r0 = row0 + wm * 64 + mt * 16 + g;
                if (r0 < M)
                    *(__half2*)&O[r0 * D + c0] =
                        __floats2half2_rn(acc[mt][nt][0] + bias.x, acc[mt][nt][1] + bias.y);
                if (r0 + 8 < M)
                    *(__half2*)&O[(r0 + 8) * D + c0] =
                        __floats2half2_rn(acc[mt][nt][2] + bias.x, acc[mt][nt][3] + bias.y);
            }
        } else {
            float* O = (sel == 0) ? Oq : Oo;
            #pragma unroll
            for (int mt = 0; mt < 4; mt++) {
                int r0 = row0 + wm * 64 + mt * 16 + g;
                if (r0 < M)
                    *(float2*)&O[r0 * D + c0] =
                        make_float2(acc[mt][nt][0] + bias.x, acc[mt][nt][1] + bias.y);
                if (r0 + 8 < M)
                    *(float2*)&O[(r0 + 8) * D + c0] =
                        make_float2(acc[mt][nt][2] + bias.x, acc[mt][nt][3] + bias.y);
            }
        }
    }
}

// ---------------- node aggregation (warp per node, CSR gather, fp16 k/v) -----
template <int D>
__global__ __launch_bounds__(256)
void node_agg(const float* __restrict__ q, const __half* __restrict__ kh,
              const __half* __restrict__ vh, float* __restrict__ o,
              const int* __restrict__ offs, const int* __restrict__ deg,
              const int* __restrict__ csrc, const float* __restrict__ ca,
              const float* __restrict__ We, float* __restrict__ stats, float scale) {
    constexpr int C = D / 32;   // floats per lane (8 for D0, 2 for DIMV)
    __shared__ float ssu[D], ssq[D];
    int t = threadIdx.x;
    int lane = t & 31;
    for (int i = t; i < D; i += 256) { ssu[i] = 0.f; ssq[i] = 0.f; }
    __syncthreads();

    int col[C];
    if constexpr (D == 256) {
        #pragma unroll
        for (int i = 0; i < 4; i++) { col[i] = lane * 4 + i; col[4 + i] = 128 + lane * 4 + i; }
    } else {
        #pragma unroll
        for (int i = 0; i < C; i++) col[i] = lane * C + i;
    }

    float we[C];
    #pragma unroll
    for (int i = 0; i < C; i++) we[i] = We[col[i]];

    float su[C] = {}, sq[C] = {};

    int wg = blockIdx.x * 8 + (t >> 5);
    int tw = gridDim.x * 8;

    for (int n = wg; n < NN; n += tw) {
        float qr[C], acc[C] = {};
        float s = 0.f;
        if constexpr (D == 256) {
            float4 a0 = *(const float4*)&q[n * D + lane * 4];
            float4 a1 = *(const float4*)&q[n * D + 128 + lane * 4];
            qr[0] = a0.x; qr[1] = a0.y; qr[2] = a0.z; qr[3] = a0.w;
            qr[4] = a1.x; qr[5] = a1.y; qr[6] = a1.z; qr[7] = a1.w;
        } else {
            float2 a0 = *(const float2*)&q[n * D + lane * 2];
            qr[0] = a0.x; qr[1] = a0.y;
        }
        int jb = offs[n], je = jb + deg[n];
        for (int j = jb; j < je; j++) {
            int src = __ldg(&csrc[j]);
            float a = __ldg(&ca[j]);
            float kr[C], vr[C];
            if constexpr (D == 256) {
                uint2 ku0 = *(const uint2*)&kh[src * D + lane * 4];
                uint2 ku1 = *(const uint2*)&kh[src * D + 128 + lane * 4];
                uint2 vu0 = *(const uint2*)&vh[src * D + lane * 4];
                uint2 vu1 = *(const uint2*)&vh[src * D + 128 + lane * 4];
                float2 f;
                f = __half22float2(*(__half2*)&ku0.x); kr[0] = f.x; kr[1] = f.y;
                f = __half22float2(*(__half2*)&ku0.y); kr[2] = f.x; kr[3] = f.y;
                f = __half22float2(*(__half2*)&ku1.x); kr[4] = f.x; kr[5] = f.y;
                f = __half22float2(*(__half2*)&ku1.y); kr[6] = f.x; kr[7] = f.y;
                f = __half22float2(*(__half2*)&vu0.x); vr[0] = f.x; vr[1] = f.y;
                f = __half22float2(*(__half2*)&vu0.y); vr[2] = f.x; vr[3] = f.y;
                f = __half22float2(*(__half2*)&vu1.x); vr[4] = f.x; vr[5] = f.y;
                f = __half22float2(*(__half2*)&vu1.y); vr[6] = f.x; vr[7] = f.y;
            } else {
                uint32_t ku = *(const uint32_t*)&kh[src * D + lane * 2];
                uint32_t vu = *(const uint32_t*)&vh[src * D + lane * 2];
                float2 f;
                f = __half22float2(*(__half2*)&ku); kr[0] = f.x; kr[1] = f.y;
                f = __half22float2(*(__half2*)&vu); vr[0] = f.x; vr[1] = f.y;
            }
            float part = 0.f;
            #pragma unroll
            for (int i = 0; i < C; i++) part += qr[i] * fmaf(a, we[i], kr[i]);
            #pragma unroll
            for (int off = 16; off > 0; off >>= 1)
                part += __shfl_xor_sync(0xffffffffu, part, off);
            float p = expf(part * scale);
            s += p;
            #pragma unroll
            for (int i = 0; i < C; i++) acc[i] = fmaf(p, fmaf(a, we[i], vr[i]), acc[i]);
        }
        float inv = 1.f / (s + 1e-16f);
        float val[C];
        if constexpr (D == 256) {
            float4 s0 = *(const float4*)&o[n * D + lane * 4];
            float4 s1 = *(const float4*)&o[n * D + 128 + lane * 4];
            val[0] = s0.x + acc[0] * inv; val[1] = s0.y + acc[1] * inv;
            val[2] = s0.z + acc[2] * inv; val[3] = s0.w + acc[3] * inv;
            val[4] = s1.x + acc[4] * inv; val[5] = s1.y + acc[5] * inv;
            val[6] = s1.z + acc[6] * inv; val[7] = s1.w + acc[7] * inv;
            *(float4*)&o[n * D + lane * 4] = make_float4(val[0], val[1], val[2], val[3]);
            *(float4*)&o[n * D + 128 + lane * 4] = make_float4(val[4], val[5], val[6], val[7]);
        } else {
            float2 s0 = *(const float2*)&o[n * D + lane * 2];
            val[0] = s0.x + acc[0] * inv; val[1] = s0.y + acc[1] * inv;
            *(float2*)&o[n * D + lane * 2] = make_float2(val[0], val[1]);
        }
        #pragma unroll
        for (int i = 0; i < C; i++) { su[i] += val[i]; sq[i] += val[i] * val[i]; }
    }

    #pragma unroll
    for (int i = 0; i < C; i++) {
        atomicAdd(&ssu[col[i]], su[i]);
        atomicAdd(&ssq[col[i]], sq[i]);
    }
    __syncthreads();
    for (int i = t; i < D; i += 256) {
        atomicAdd(&stats[i], ssu[i]);
        atomicAdd(&stats[D + i], ssq[i]);
    }
}

// ---------------- batch norm -------------------------------------------------
__global__ void bn_finalize(float* stats, int Nrows, int D) {
    int c = threadIdx.x;
    if (c >= D) return;
    float mu = stats[c] / (float)Nrows;
    float var = stats[D + c] / (float)Nrows - mu * mu;
    stats[c] = mu;
    stats[D + c] = rsqrtf(var + 1e-5f);
}

// normalize; write xs slab; run-length-batched pool accumulation
template <int D>
__global__ void bn_apply(const float* __restrict__ X, const float* __restrict__ stats,
                         const float* __restrict__ gamma, const float* __restrict__ beta,
                         float* __restrict__ xs, float* __restrict__ pool,
                         const int* __restrict__ batch, int col_off) {
    constexpr int CG = D / 4;        // col groups (64 / 16)
    constexpr int RL = 256 / CG;     // row lanes  (4 / 16)
    constexpr int CHUNK = 16;        // consecutive rows per thread
    int t = threadIdx.x;
    int cg = t % CG, rl = t / CG;
    int r0 = blockIdx.x * (RL * CHUNK) + rl * CHUNK;
    int c4 = cg * 4;
    float4 mu = *(const float4*)&stats[c4];
    float4 rs = *(const float4*)&stats[D + c4];
    float4 gm = *(const float4*)&gamma[c4];
    float4 bt = *(const float4*)&beta[c4];
    float4 acc = make_float4(0.f, 0.f, 0.f, 0.f);
    int curb = -1;
    for (int i = 0; i < CHUNK; i++) {
        int r = r0 + i;
        if (r >= NN) break;
        int b = __ldg(&batch[r]);
        if (b != curb) {
            if (curb >= 0) red_add_v4(&pool[curb * OUTW + col_off + c4], acc);
            acc = make_float4(0.f, 0.f, 0.f, 0.f);
            curb = b;
        }
        float4 xv = *(const float4*)&X[r * D + c4];
        float4 val;
        val.x = gm.x * (xv.x - mu.x) * rs.x + bt.x;
        val.y = gm.y * (xv.y - mu.y) * rs.y + bt.y;
        val.z = gm.z * (xv.z - mu.z) * rs.z + bt.z;
        val.w = gm.w * (xv.w - mu.w) * rs.w + bt.w;
        *(float4*)&xs[r * OUTW + col_off + c4] = val;
        acc.x += val.x; acc.y += val.y; acc.z += val.z; acc.w += val.w;
    }
    if (curb >= 0) red_add_v4(&pool[curb * OUTW + col_off + c4], acc);
}

__global__ void pool_div(float* pool, const float* __restrict__ cnt) {
    int i = blockIdx.x * blockDim.x + threadIdx.x;
    if (i >= GG * OUTW) return;
    pool[i] /= fmaxf(cnt[i / OUTW], 1.f);
}

// ---------------- launch -----------------------------------------------------
extern "C" void kernel_launch(void* const* d_in, const int* in_sizes, int n_in,
                              void* d_out, int out_size) {
    const float* x     = (const float*)d_in[0];
    const int*   ei    = (const int*)  d_in[1];
    const float* ea    = (const float*)d_in[2];
    const int*   batch = (const int*)  d_in[3];
    const float* Wq0 = (const float*)d_in[4];  const float* bq0 = (const float*)d_in[5];
    const float* Wk0 = (const float*)d_in[6];  const float* bk0 = (const float*)d_in[7];
    const float* Wv0 = (const float*)d_in[8];  const float* bv0 = (const float*)d_in[9];
    const float* We0 = (const float*)d_in[10];
    const float* Ws0 = (const float*)d_in[11]; const float* bs0 = (const float*)d_in[12];
    const float* gamma0 = (const float*)d_in[13]; const float* beta0 = (const float*)d_in[14];
    const float* Wq1 = (const float*)d_in[15]; const float* bq1 = (const float*)d_in[16];
    const float* Wk1 = (const float*)d_in[17]; const float* bk1 = (const float*)d_in[18];
    const float* Wv1 = (const float*)d_in[19]; const float* bv1 = (const float*)d_in[20];
    const float* We1 = (const float*)d_in[21];
    const float* Ws1 = (const float*)d_in[22]; const float* bs1 = (const float*)d_in[23];
    const float* gamma1 = (const float*)d_in[24]; const float* beta1 = (const float*)d_in[25];

    float* out  = (float*)d_out;
    float* pool = out;
    float* xs   = out + GG * OUTW;

    float *q, *o, *statsA, *statsB, *cnt, *Wp0, *bp0, *Wp1, *bp1, *ca;
    __half *kh, *vh;
    int *deg, *offs, *csrc;
    cudaGetSymbolAddress((void**)&q, g_q);
    cudaGetSymbolAddress((void**)&kh, g_kh);
    cudaGetSymbolAddress((void**)&vh, g_vh);
    cudaGetSymbolAddress((void**)&o, g_o);
    cudaGetSymbolAddress((void**)&deg, g_deg);
    cudaGetSymbolAddress((void**)&offs, g_offs);
    cudaGetSymbolAddress((void**)&csrc, g_csrc);
    cudaGetSymbolAddress((void**)&ca, g_ca);
    cudaGetSymbolAddress((void**)&statsA, g_statsA);
    cudaGetSymbolAddress((void**)&statsB, g_statsB);
    cudaGetSymbolAddress((void**)&cnt, g_cnt);
    cudaGetSymbolAddress((void**)&Wp0, g_Wp0);
    cudaGetSymbolAddress((void**)&bp0, g_bp0);
    cudaGetSymbolAddress((void**)&Wp1, g_Wp1);
    cudaGetSymbolAddress((void**)&bp1, g_bp1);

    const int TB = 256;

    // 0: prep   1: hist   2: scan   3: gemm L0 (profiled)   4: fill_csr
    prep<<<512, TB>>>(pool, cnt, deg, statsA, statsB,
                      Wq0, Wk0, Wv0, Ws0, bq0, bk0, bv0, bs0,
                      Wq1, Wk1, Wv1, Ws1, bq1, bk1, bv1, bs1,
                      Wp0, bp0, Wp1, bp1);
    hist_count<<<(EE + TB - 1) / TB, TB>>>(ei, deg, batch, cnt);
    scan_kernel<<<1, 1024>>>(deg, offs);

    dim3 g0(4 * D0 / BN, (NN + BM - 1) / BM);
    mma_gemm4<<<g0, 256>>>(x, Wp0, bp0, q, kh, vh, o, NN, FIN, FIN, D0);

    fill_csr<<<(EE + TB - 1) / TB, TB>>>(ei, ea, offs, deg, csrc, ca);

    node_agg<D0><<<1184, 256>>>(q, kh, vh, o, offs, deg, csrc, ca, We0, statsA, 1.f / 16.f);

    bn_finalize<<<1, D0>>>(statsA, NN, D0);
    bn_apply<D0><<<(NN + 63) / 64, 256>>>(o, statsA, gamma0, beta0, xs, pool, batch, 0);

    // layer 1 (A = xs slab, lda=OUTW)
    dim3 g1(4 * DIMV / BN, (NN + BM - 1) / BM);
    mma_gemm4<<<g1, 256>>>(xs, Wp1, bp1, q, kh, vh, o, NN, D0, OUTW, DIMV);

    node_agg<DIMV><<<1184, 256>>>(q, kh, vh, o, offs, deg, csrc, ca, We1, statsB, 1.f / 8.f);

    bn_finalize<<<1, DIMV>>>(statsB, NN, DIMV);
    bn_apply<DIMV><<<(NN + 255) / 256, 256>>>(o, statsB, gamma1, beta1, xs, pool, batch, D0);

    pool_div<<<(GG * OUTW + TB - 1) / TB, TB>>>(pool, cnt);
}

// round 6
// speedup vs baseline: 3.0984x; 1.0947x over previous
#include <cuda_runtime.h>
#include <cuda_fp16.h>
#include <cstdint>

#define NN   50000
#define EE   800000
#define FIN  128
#define D0   256
#define DIMV 64
#define GG   256
#define OUTW 320   // D0 + DIMV

// ---------------- scratch (device globals; no allocation) ----------------
__device__ float  g_q[NN * D0];
__device__ __half g_kh[NN * D0];
__device__ __half g_vh[NN * D0];
__device__ float  g_o[NN * D0];
__device__ int    g_deg[NN];
__device__ int    g_offs[NN];
__device__ int    g_csrc[EE];
__device__ float  g_ca[EE];
__device__ float  g_statsA[2 * D0];
__device__ float  g_statsB[2 * DIMV];
__device__ float  g_cnt[GG];
__device__ float  g_Wp0[FIN * 4 * D0];
__device__ float  g_bp0[4 * D0];
__device__ float  g_Wp1[D0 * 4 * DIMV];
__device__ float  g_bp1[4 * DIMV];

// ---------------- helpers ----------------
__device__ __forceinline__ void red_add_v4(float* ptr, float4 v) {
    asm volatile("red.global.add.v4.f32 [%0], {%1,%2,%3,%4};"
                 :: "l"(ptr), "f"(v.x), "f"(v.y), "f"(v.z), "f"(v.w) : "memory");
}
__device__ __forceinline__ uint32_t smem_u32(const void* p) {
    return (uint32_t)__cvta_generic_to_shared(p);
}
__device__ __forceinline__ void ldsm_x4(uint32_t& r0, uint32_t& r1, uint32_t& r2,
                                        uint32_t& r3, uint32_t addr) {
    asm volatile("ldmatrix.sync.aligned.m8n8.x4.shared.b16 {%0,%1,%2,%3}, [%4];"
                 : "=r"(r0), "=r"(r1), "=r"(r2), "=r"(r3) : "r"(addr));
}
__device__ __forceinline__ void ldsm_x4_t(uint32_t& r0, uint32_t& r1, uint32_t& r2,
                                          uint32_t& r3, uint32_t addr) {
    asm volatile("ldmatrix.sync.aligned.m8n8.x4.trans.shared.b16 {%0,%1,%2,%3}, [%4];"
                 : "=r"(r0), "=r"(r1), "=r"(r2), "=r"(r3) : "r"(addr));
}
__device__ __forceinline__ void mma_f16(float& c0, float& c1, float& c2, float& c3,
                                        uint32_t a0, uint32_t a1, uint32_t a2, uint32_t a3,
                                        uint32_t b0, uint32_t b1) {
    asm volatile("mma.sync.aligned.m16n8k16.row.col.f32.f16.f16.f32 "
                 "{%0,%1,%2,%3}, {%4,%5,%6,%7}, {%8,%9}, {%0,%1,%2,%3};"
                 : "+f"(c0), "+f"(c1), "+f"(c2), "+f"(c3)
                 : "r"(a0), "r"(a1), "r"(a2), "r"(a3), "r"(b0), "r"(b1));
}

// ---------------- prep: all zeroing + weight packing in ONE launch -----------
__global__ void prep(float* pool, float* cnt, int* deg, float* statsA, float* statsB,
                     const float* __restrict__ Wq0, const float* __restrict__ Wk0,
                     const float* __restrict__ Wv0, const float* __restrict__ Ws0,
                     const float* __restrict__ bq0, const float* __restrict__ bk0,
                     const float* __restrict__ bv0, const float* __restrict__ bs0,
                     const float* __restrict__ Wq1, const float* __restrict__ Wk1,
                     const float* __restrict__ Wv1, const float* __restrict__ Ws1,
                     const float* __restrict__ bq1, const float* __restrict__ bk1,
                     const float* __restrict__ bv1, const float* __restrict__ bs1,
                     float* Wp0, float* bp0, float* Wp1, float* bp1) {
    int gs = gridDim.x * blockDim.x;
    int i0 = blockIdx.x * blockDim.x + threadIdx.x;
    for (int i = i0; i < GG * OUTW; i += gs) pool[i] = 0.f;
    for (int i = i0; i < GG; i += gs) cnt[i] = 0.f;
    for (int i = i0; i < NN; i += gs) deg[i] = 0;
    for (int i = i0; i < 2 * D0; i += gs) statsA[i] = 0.f;
    for (int i = i0; i < 2 * DIMV; i += gs) statsB[i] = 0.f;
    for (int i = i0; i < FIN * 4 * D0; i += gs) {
        int kk = i / (4 * D0), c = i % (4 * D0);
        int sel = c / D0, cc = c % D0;
        const float* W = sel == 0 ? Wq0 : sel == 1 ? Wk0 : sel == 2 ? Wv0 : Ws0;
        Wp0[i] = W[kk * D0 + cc];
    }
    for (int i = i0; i < 4 * D0; i += gs) {
        int sel = i / D0, cc = i % D0;
        const float* b = sel == 0 ? bq0 : sel == 1 ? bk0 : sel == 2 ? bv0 : bs0;
        bp0[i] = b[cc];
    }
    for (int i = i0; i < D0 * 4 * DIMV; i += gs) {
        int kk = i / (4 * DIMV), c = i % (4 * DIMV);
        int sel = c / DIMV, cc = c % DIMV;
        const float* W = sel == 0 ? Wq1 : sel == 1 ? Wk1 : sel == 2 ? Wv1 : Ws1;
        Wp1[i] = W[kk * DIMV + cc];
    }
    for (int i = i0; i < 4 * DIMV; i += gs) {
        int sel = i / DIMV, cc = i % DIMV;
        const float* b = sel == 0 ? bq1 : sel == 1 ? bk1 : sel == 2 ? bv1 : bs1;
        bp1[i] = b[cc];
    }
}

// ---------------- CSR build --------------------------------------------------
__global__ void hist_count(const int* __restrict__ ei, int* deg,
                           const int* __restrict__ batch, float* cnt) {
    int i = blockIdx.x * blockDim.x + threadIdx.x;
    if (i < EE) atomicAdd(&deg[ei[EE + i]], 1);
    if (i < NN) atomicAdd(&cnt[batch[i]], 1.f);
}

__global__ void scan_kernel(int* deg, int* offs) {   // 1 block, 1024 threads
    __shared__ int ps[1024];
    int t = threadIdx.x;
    const int CH = (NN + 1023) / 1024;
    int base = t * CH;
    int sum = 0;
    for (int i = 0; i < CH; i++) {
        int idx = base + i;
        if (idx < NN) sum += deg[idx];
    }
    ps[t] = sum;
    __syncthreads();
    for (int off = 1; off < 1024; off <<= 1) {
        int v = (t >= off) ? ps[t - off] : 0;
        __syncthreads();
        ps[t] += v;
        __syncthreads();
    }
    int run = (t > 0) ? ps[t - 1] : 0;
    for (int i = 0; i < CH; i++) {
        int idx = base + i;
        if (idx < NN) {
            offs[idx] = run;
            run += deg[idx];
            deg[idx] = 0;
        }
    }
}

__global__ void fill_csr(const int* __restrict__ ei, const float* __restrict__ ea,
                         const int* __restrict__ offs, int* deg,
                         int* csrc, float* ca) {
    int e = blockIdx.x * blockDim.x + threadIdx.x;
    if (e >= EE) return;
    int dst = ei[EE + e];
    int slot = offs[dst] + atomicAdd(&deg[dst], 1);
    csrc[slot] = ei[e];
    ca[slot] = ea[e];
}

// ---------------- fp16 tensor-core GEMM --------------------------------------
// [M, 4D] = A @ Wp + bp; col groups: 0 -> float q, 1 -> half k, 2 -> half v,
// 3 -> float skip. 128x128 tile, BK=32, 8 warps (2x4), warp tile 64x32.
#define BM 128
#define BN 128
#define BKH 32
#define APITCH 40    // halves; 80B row stride -> ldmatrix conflict-free
#define BPITCH 136   // halves; 272B row stride -> ldmatrix conflict-free

__global__ __launch_bounds__(256)
void hgemm4(const float* __restrict__ A, const float* __restrict__ Wp,
            const float* __restrict__ bp,
            float* __restrict__ Oq, __half* __restrict__ Ok,
            __half* __restrict__ Ov, float* __restrict__ Oo,
            int M, int K, int lda, int D) {
    const int Nc = 4 * D;
    __shared__ __half As[BM][APITCH];
    __shared__ __half Bs[BKH][BPITCH];

    int t = threadIdx.x;
    int lane = t & 31;
    int warp = t >> 5;
    int wm = warp >> 2;          // 0..1
    int wn = warp & 3;           // 0..3
    int g = lane >> 2;
    int t4 = lane & 3;
    int row0 = blockIdx.y * BM;
    int col0 = blockIdx.x * BN;

    float acc[4][4][4] = {};

    // global->smem mapping
    int lar = t >> 3;            // A row 0..31 step (4 rows per thread via i loop)
    int lac = (t & 7) * 4;       // A col group
    int lbr = t >> 5;            // B row base
    int lbc = (t & 31) * 4;      // B col group

    // ldmatrix lane addressing (precomputed pieces)
    int a_row_l = lane & 15;
    int a_koff = (lane >> 4) * 8;
    int b_krow_l = ((lane >> 3) & 1) * 8 + (lane & 7);
    int b_noff = (lane >> 4) * 8;

    for (int k0 = 0; k0 < K; k0 += BKH) {
        // A tile: 128 rows x 32 k floats -> half
        #pragma unroll
        for (int i = 0; i < 4; i++) {
            int row = lar + i * 32;
            int gr = row0 + row;
            float4 v = (gr < M) ? *(const float4*)&A[gr * lda + k0 + lac]
                                : make_float4(0.f, 0.f, 0.f, 0.f);
            __half2 h0 = __floats2half2_rn(v.x, v.y);
            __half2 h1 = __floats2half2_rn(v.z, v.w);
            *(uint2*)&As[row][lac] = make_uint2(*(uint32_t*)&h0, *(uint32_t*)&h1);
        }
        // B tile: 32 k x 128 cols floats -> half
        #pragma unroll
        for (int i = 0; i < 4; i++) {
            int brow = lbr + i * 8;
            float4 v = *(const float4*)&Wp[(k0 + brow) * Nc + col0 + lbc];
            __half2 h0 = __floats2half2_rn(v.x, v.y);
            __half2 h1 = __floats2half2_rn(v.z, v.w);
            *(uint2*)&Bs[brow][lbc] = make_uint2(*(uint32_t*)&h0, *(uint32_t*)&h1);
        }
        __syncthreads();

        #pragma unroll
        for (int ks = 0; ks < 2; ks++) {
            int kk = ks * 16;
            uint32_t af[4][4], bf[4][2];
            #pragma unroll
            for (int mt = 0; mt < 4; mt++) {
                int rb = wm * 64 + mt * 16;
                uint32_t addr = smem_u32(&As[rb + a_row_l][kk + a_koff]);
                ldsm_x4(af[mt][0], af[mt][1], af[mt][2], af[mt][3], addr);
            }
            #pragma unroll
            for (int p = 0; p < 2; p++) {
                int n0 = wn * 32 + p * 16;
                uint32_t addr = smem_u32(&Bs[kk + b_krow_l][n0 + b_noff]);
                ldsm_x4_t(bf[2 * p][0], bf[2 * p][1], bf[2 * p + 1][0], bf[2 * p + 1][1],
                          addr);
            }
            #pragma unroll
            for (int mt = 0; mt < 4; mt++)
                #pragma unroll
                for (int nt = 0; nt < 4; nt++)
                    mma_f16(acc[mt][nt][0], acc[mt][nt][1], acc[mt][nt][2], acc[mt][nt][3],
                            af[mt][0], af[mt][1], af[mt][2], af[mt][3],
                            bf[nt][0], bf[nt][1]);
        }
        __syncthreads();
    }

    #pragma unroll
    for (int nt = 0; nt < 4; nt++) {
        int cg = col0 + wn * 32 + nt * 8;
        int sel = cg / D;
        int cc = cg % D;
        int c0 = cc + 2 * t4;
        float2 bias = *(const float2*)&bp[cg + 2 * t4];
        if (sel == 1 || sel == 2) {
            __half* O = (sel == 1) ? Ok : Ov;
            #pragma unroll
            for (int mt = 0; mt < 4; mt++) {
                int r0 = row0 + wm * 64 + mt * 16 + g;
                if (r0 < M)
                    *(__half2*)&O[r0 * D + c0] =
                        __floats2half2_rn(acc[mt][nt][0] + bias.x, acc[mt][nt][1] + bias.y);
                if (r0 + 8 < M)
                    *(__half2*)&O[(r0 + 8) * D + c0] =
                        __floats2half2_rn(acc[mt][nt][2] + bias.x, acc[mt][nt][3] + bias.y);
            }
        } else {
            float* O = (sel == 0) ? Oq : Oo;
            #pragma unroll
            for (int mt = 0; mt < 4; mt++) {
                int r0 = row0 + wm * 64 + mt * 16 + g;
                if (r0 < M)
                    *(float2*)&O[r0 * D + c0] =
                        make_float2(acc[mt][nt][0] + bias.x, acc[mt][nt][1] + bias.y);
                if (r0 + 8 < M)
                    *(float2*)&O[(r0 + 8) * D + c0] =
                        make_float2(acc[mt][nt][2] + bias.x, acc[mt][nt][3] + bias.y);
            }
        }
    }
}

// ---------------- node aggregation (warp per node, 2-edge pipelined) ---------
template <int D>
__device__ __forceinline__ void loadkv(const __half* __restrict__ kh,
                                       const __half* __restrict__ vh,
                                       int src, int lane, float* kr, float* vr) {
    if constexpr (D == 256) {
        uint2 ku0 = *(const uint2*)&kh[src * D + lane * 4];
        uint2 ku1 = *(const uint2*)&kh[src * D + 128 + lane * 4];
        uint2 vu0 = *(const uint2*)&vh[src * D + lane * 4];
        uint2 vu1 = *(const uint2*)&vh[src * D + 128 + lane * 4];
        float2 f;
        f = __half22float2(*(__half2*)&ku0.x); kr[0] = f.x; kr[1] = f.y;
        f = __half22float2(*(__half2*)&ku0.y); kr[2] = f.x; kr[3] = f.y;
        f = __half22float2(*(__half2*)&ku1.x); kr[4] = f.x; kr[5] = f.y;
        f = __half22float2(*(__half2*)&ku1.y); kr[6] = f.x; kr[7] = f.y;
        f = __half22float2(*(__half2*)&vu0.x); vr[0] = f.x; vr[1] = f.y;
        f = __half22float2(*(__half2*)&vu0.y); vr[2] = f.x; vr[3] = f.y;
        f = __half22float2(*(__half2*)&vu1.x); vr[4] = f.x; vr[5] = f.y;
        f = __half22float2(*(__half2*)&vu1.y); vr[6] = f.x; vr[7] = f.y;
    } else {
        uint32_t ku = *(const uint32_t*)&kh[src * D + lane * 2];
        uint32_t vu = *(const uint32_t*)&vh[src * D + lane * 2];
        float2 f;
        f = __half22float2(*(__half2*)&ku); kr[0] = f.x; kr[1] = f.y;
        f = __half22float2(*(__half2*)&vu); vr[0] = f.x; vr[1] = f.y;
    }
}

template <int D>
__global__ __launch_bounds__(256)
void node_agg(const float* __restrict__ q, const __half* __restrict__ kh,
              const __half* __restrict__ vh, float* __restrict__ o,
              const int* __restrict__ offs, const int* __restrict__ deg,
              const int* __restrict__ csrc, const float* __restrict__ ca,
              const float* __restrict__ We, float* __restrict__ stats, float scale) {
    constexpr int C = D / 32;
    __shared__ float ssu[D], ssq[D];
    int t = threadIdx.x;
    int lane = t & 31;
    for (int i = t; i < D; i += 256) { ssu[i] = 0.f; ssq[i] = 0.f; }
    __syncthreads();

    int col[C];
    if constexpr (D == 256) {
        #pragma unroll
        for (int i = 0; i < 4; i++) { col[i] = lane * 4 + i; col[4 + i] = 128 + lane * 4 + i; }
    } else {
        #pragma unroll
        for (int i = 0; i < C; i++) col[i] = lane * C + i;
    }

    float we[C];
    #pragma unroll
    for (int i = 0; i < C; i++) we[i] = We[col[i]];

    float su[C] = {}, sq[C] = {};

    int wg = blockIdx.x * 8 + (t >> 5);
    int tw = gridDim.x * 8;

    for (int n = wg; n < NN; n += tw) {
        float qr[C], acc[C] = {};
        float s = 0.f;
        if constexpr (D == 256) {
            float4 a0 = *(const float4*)&q[n * D + lane * 4];
            float4 a1 = *(const float4*)&q[n * D + 128 + lane * 4];
            qr[0] = a0.x; qr[1] = a0.y; qr[2] = a0.z; qr[3] = a0.w;
            qr[4] = a1.x; qr[5] = a1.y; qr[6] = a1.z; qr[7] = a1.w;
        } else {
            float2 a0 = *(const float2*)&q[n * D + lane * 2];
            qr[0] = a0.x; qr[1] = a0.y;
        }
        int jb = offs[n], je = jb + deg[n];
        int j = jb;
        for (; j + 2 <= je; j += 2) {
            int s0 = __ldg(&csrc[j]), s1 = __ldg(&csrc[j + 1]);
            float a0 = __ldg(&ca[j]), a1 = __ldg(&ca[j + 1]);
            float kr0[C], vr0[C], kr1[C], vr1[C];
            loadkv<D>(kh, vh, s0, lane, kr0, vr0);
            loadkv<D>(kh, vh, s1, lane, kr1, vr1);
            float pa = 0.f, pb = 0.f;
            #pragma unroll
            for (int i = 0; i < C; i++) {
                pa += qr[i] * fmaf(a0, we[i], kr0[i]);
                pb += qr[i] * fmaf(a1, we[i], kr1[i]);
            }
            #pragma unroll
            for (int off = 16; off > 0; off >>= 1) {
                pa += __shfl_xor_sync(0xffffffffu, pa, off);
                pb += __shfl_xor_sync(0xffffffffu, pb, off);
            }
            float p0 = expf(pa * scale);
            float p1 = expf(pb * scale);
            s += p0 + p1;
            #pragma unroll
            for (int i = 0; i < C; i++) {
                acc[i] = fmaf(p0, fmaf(a0, we[i], vr0[i]), acc[i]);
                acc[i] = fmaf(p1, fmaf(a1, we[i], vr1[i]), acc[i]);
            }
        }
        if (j < je) {
            int s0 = __ldg(&csrc[j]);
            float a0 = __ldg(&ca[j]);
            float kr0[C], vr0[C];
            loadkv<D>(kh, vh, s0, lane, kr0, vr0);
            float pa = 0.f;
            #pragma unroll
            for (int i = 0; i < C; i++) pa += qr[i] * fmaf(a0, we[i], kr0[i]);
            #pragma unroll
            for (int off = 16; off > 0; off >>= 1)
                pa += __shfl_xor_sync(0xffffffffu, pa, off);
            float p0 = expf(pa * scale);
            s += p0;
            #pragma unroll
            for (int i = 0; i < C; i++)
                acc[i] = fmaf(p0, fmaf(a0, we[i], vr0[i]), acc[i]);
        }
        float inv = 1.f / (s + 1e-16f);
        float val[C];
        if constexpr (D == 256) {
            float4 s0 = *(const float4*)&o[n * D + lane * 4];
            float4 s1 = *(const float4*)&o[n * D + 128 + lane * 4];
            val[0] = s0.x + acc[0] * inv; val[1] = s0.y + acc[1] * inv;
            val[2] = s0.z + acc[2] * inv; val[3] = s0.w + acc[3] * inv;
            val[4] = s1.x + acc[4] * inv; val[5] = s1.y + acc[5] * inv;
            val[6] = s1.z + acc[6] * inv; val[7] = s1.w + acc[7] * inv;
            *(float4*)&o[n * D + lane * 4] = make_float4(val[0], val[1], val[2], val[3]);
            *(float4*)&o[n * D + 128 + lane * 4] = make_float4(val[4], val[5], val[6], val[7]);
        } else {
            float2 s0 = *(const float2*)&o[n * D + lane * 2];
            val[0] = s0.x + acc[0] * inv; val[1] = s0.y + acc[1] * inv;
            *(float2*)&o[n * D + lane * 2] = make_float2(val[0], val[1]);
        }
        #pragma unroll
        for (int i = 0; i < C; i++) { su[i] += val[i]; sq[i] += val[i] * val[i]; }
    }

    #pragma unroll
    for (int i = 0; i < C; i++) {
        atomicAdd(&ssu[col[i]], su[i]);
        atomicAdd(&ssq[col[i]], sq[i]);
    }
    __syncthreads();
    for (int i = t; i < D; i += 256) {
        atomicAdd(&stats[i], ssu[i]);
        atomicAdd(&stats[D + i], ssq[i]);
    }
}

// ---------------- batch norm -------------------------------------------------
__global__ void bn_finalize(float* stats, int Nrows, int D) {
    int c = threadIdx.x;
    if (c >= D) return;
    float mu = stats[c] / (float)Nrows;
    float var = stats[D + c] / (float)Nrows - mu * mu;
    stats[c] = mu;
    stats[D + c] = rsqrtf(var + 1e-5f);
}

template <int D>
__global__ void bn_apply(const float* __restrict__ X, const float* __restrict__ stats,
                         const float* __restrict__ gamma, const float* __restrict__ beta,
                         float* __restrict__ xs, float* __restrict__ pool,
                         const int* __restrict__ batch, int col_off) {
    constexpr int CG = D / 4;
    constexpr int RL = 256 / CG;
    constexpr int CHUNK = 16;
    int t = threadIdx.x;
    int cg = t % CG, rl = t / CG;
    int r0 = blockIdx.x * (RL * CHUNK) + rl * CHUNK;
    int c4 = cg * 4;
    float4 mu = *(const float4*)&stats[c4];
    float4 rs = *(const float4*)&stats[D + c4];
    float4 gm = *(const float4*)&gamma[c4];
    float4 bt = *(const float4*)&beta[c4];
    float4 acc = make_float4(0.f, 0.f, 0.f, 0.f);
    int curb = -1;
    for (int i = 0; i < CHUNK; i++) {
        int r = r0 + i;
        if (r >= NN) break;
        int b = __ldg(&batch[r]);
        if (b != curb) {
            if (curb >= 0) red_add_v4(&pool[curb * OUTW + col_off + c4], acc);
            acc = make_float4(0.f, 0.f, 0.f, 0.f);
            curb = b;
        }
        float4 xv = *(const float4*)&X[r * D + c4];
        float4 val;
        val.x = gm.x * (xv.x - mu.x) * rs.x + bt.x;
        val.y = gm.y * (xv.y - mu.y) * rs.y + bt.y;
        val.z = gm.z * (xv.z - mu.z) * rs.z + bt.z;
        val.w = gm.w * (xv.w - mu.w) * rs.w + bt.w;
        *(float4*)&xs[r * OUTW + col_off + c4] = val;
        acc.x += val.x; acc.y += val.y; acc.z += val.z; acc.w += val.w;
    }
    if (curb >= 0) red_add_v4(&pool[curb * OUTW + col_off + c4], acc);
}

__global__ void pool_div(float* pool, const float* __restrict__ cnt) {
    int i = blockIdx.x * blockDim.x + threadIdx.x;
    if (i >= GG * OUTW) return;
    pool[i] /= fmaxf(cnt[i / OUTW], 1.f);
}

// ---------------- launch -----------------------------------------------------
extern "C" void kernel_launch(void* const* d_in, const int* in_sizes, int n_in,
                              void* d_out, int out_size) {
    const float* x     = (const float*)d_in[0];
    const int*   ei    = (const int*)  d_in[1];
    const float* ea    = (const float*)d_in[2];
    const int*   batch = (const int*)  d_in[3];
    const float* Wq0 = (const float*)d_in[4];  const float* bq0 = (const float*)d_in[5];
    const float* Wk0 = (const float*)d_in[6];  const float* bk0 = (const float*)d_in[7];
    const float* Wv0 = (const float*)d_in[8];  const float* bv0 = (const float*)d_in[9];
    const float* We0 = (const float*)d_in[10];
    const float* Ws0 = (const float*)d_in[11]; const float* bs0 = (const float*)d_in[12];
    const float* gamma0 = (const float*)d_in[13]; const float* beta0 = (const float*)d_in[14];
    const float* Wq1 = (const float*)d_in[15]; const float* bq1 = (const float*)d_in[16];
    const float* Wk1 = (const float*)d_in[17]; const float* bk1 = (const float*)d_in[18];
    const float* Wv1 = (const float*)d_in[19]; const float* bv1 = (const float*)d_in[20];
    const float* We1 = (const float*)d_in[21];
    const float* Ws1 = (const float*)d_in[22]; const float* bs1 = (const float*)d_in[23];
    const float* gamma1 = (const float*)d_in[24]; const float* beta1 = (const float*)d_in[25];

    float* out  = (float*)d_out;
    float* pool = out;
    float* xs   = out + GG * OUTW;

    float *q, *o, *statsA, *statsB, *cnt, *Wp0, *bp0, *Wp1, *bp1, *ca;
    __half *kh, *vh;
    int *deg, *offs, *csrc;
    cudaGetSymbolAddress((void**)&q, g_q);
    cudaGetSymbolAddress((void**)&kh, g_kh);
    cudaGetSymbolAddress((void**)&vh, g_vh);
    cudaGetSymbolAddress((void**)&o, g_o);
    cudaGetSymbolAddress((void**)&deg, g_deg);
    cudaGetSymbolAddress((void**)&offs, g_offs);
    cudaGetSymbolAddress((void**)&csrc, g_csrc);
    cudaGetSymbolAddress((void**)&ca, g_ca);
    cudaGetSymbolAddress((void**)&statsA, g_statsA);
    cudaGetSymbolAddress((void**)&statsB, g_statsB);
    cudaGetSymbolAddress((void**)&cnt, g_cnt);
    cudaGetSymbolAddress((void**)&Wp0, g_Wp0);
    cudaGetSymbolAddress((void**)&bp0, g_bp0);
    cudaGetSymbolAddress((void**)&Wp1, g_Wp1);
    cudaGetSymbolAddress((void**)&bp1, g_bp1);

    const int TB = 256;

    // 0: prep   1: hist   2: scan   3: gemm L0 (profiled slot)   4: fill_csr
    prep<<<512, TB>>>(pool, cnt, deg, statsA, statsB,
                      Wq0, Wk0, Wv0, Ws0, bq0, bk0, bv0, bs0,
                      Wq1, Wk1, Wv1, Ws1, bq1, bk1, bv1, bs1,
                      Wp0, bp0, Wp1, bp1);
    hist_count<<<(EE + TB - 1) / TB, TB>>>(ei, deg, batch, cnt);
    scan_kernel<<<1, 1024>>>(deg, offs);

    dim3 g0(4 * D0 / BN, (NN + BM - 1) / BM);
    hgemm4<<<g0, 256>>>(x, Wp0, bp0, q, kh, vh, o, NN, FIN, FIN, D0);

    fill_csr<<<(EE + TB - 1) / TB, TB>>>(ei, ea, offs, deg, csrc, ca);

    node_agg<D0><<<1184, 256>>>(q, kh, vh, o, offs, deg, csrc, ca, We0, statsA, 1.f / 16.f);

    bn_finalize<<<1, D0>>>(statsA, NN, D0);
    bn_apply<D0><<<(NN + 63) / 64, 256>>>(o, statsA, gamma0, beta0, xs, pool, batch, 0);

    dim3 g1(4 * DIMV / BN, (NN + BM - 1) / BM);
    hgemm4<<<g1, 256>>>(xs, Wp1, bp1, q, kh, vh, o, NN, D0, OUTW, DIMV);

    node_agg<DIMV><<<1184, 256>>>(q, kh, vh, o, offs, deg, csrc, ca, We1, statsB, 1.f / 8.f);

    bn_finalize<<<1, DIMV>>>(statsB, NN, DIMV);
    bn_apply<DIMV><<<(NN + 255) / 256, 256>>>(o, statsB, gamma1, beta1, xs, pool, batch, D0);

    pool_div<<<(GG * OUTW + TB - 1) / TB, TB>>>(pool, cnt);
}

// round 7
// speedup vs baseline: 3.4817x; 1.1237x over previous
#include <cuda_runtime.h>
#include <cuda_fp16.h>
#include <cstdint>

#define NN   50000
#define EE   800000
#define FIN  128
#define D0   256
#define DIMV 64
#define GG   256
#define OUTW 320   // D0 + DIMV

// ---------------- scratch (device globals; no allocation) ----------------
__device__ float  g_q[NN * D0];
__device__ __half g_kh[NN * D0];
__device__ __half g_vh[NN * D0];
__device__ float  g_o[NN * D0];
__device__ __half g_xh[NN * FIN];      // fp16 copy of input x
__device__ __half g_hh[NN * D0];       // fp16 copy of normalized h0
__device__ int    g_deg[NN];
__device__ int    g_offs[NN];
__device__ int    g_csrc[EE];
__device__ float  g_ca[EE];
__device__ float  g_statsA[2 * D0];
__device__ float  g_statsB[2 * DIMV];
__device__ float  g_cnt[GG];
__device__ __half g_Wph0[FIN * 4 * D0];
__device__ float  g_bp0[4 * D0];
__device__ __half g_Wph1[D0 * 4 * DIMV];
__device__ float  g_bp1[4 * DIMV];

// ---------------- helpers ----------------
__device__ __forceinline__ void red_add_v4(float* ptr, float4 v) {
    asm volatile("red.global.add.v4.f32 [%0], {%1,%2,%3,%4};"
                 :: "l"(ptr), "f"(v.x), "f"(v.y), "f"(v.z), "f"(v.w) : "memory");
}
__device__ __forceinline__ uint32_t smem_u32(const void* p) {
    return (uint32_t)__cvta_generic_to_shared(p);
}
__device__ __forceinline__ void cp_async16(uint32_t dst, const void* src, int src_sz) {
    asm volatile("cp.async.cg.shared.global [%0], [%1], 16, %2;"
                 :: "r"(dst), "l"(src), "r"(src_sz));
}
__device__ __forceinline__ void cp_commit() {
    asm volatile("cp.async.commit_group;");
}
__device__ __forceinline__ void ldsm_x4(uint32_t& r0, uint32_t& r1, uint32_t& r2,
                                        uint32_t& r3, uint32_t addr) {
    asm volatile("ldmatrix.sync.aligned.m8n8.x4.shared.b16 {%0,%1,%2,%3}, [%4];"
                 : "=r"(r0), "=r"(r1), "=r"(r2), "=r"(r3) : "r"(addr));
}
__device__ __forceinline__ void ldsm_x4_t(uint32_t& r0, uint32_t& r1, uint32_t& r2,
                                          uint32_t& r3, uint32_t addr) {
    asm volatile("ldmatrix.sync.aligned.m8n8.x4.trans.shared.b16 {%0,%1,%2,%3}, [%4];"
                 : "=r"(r0), "=r"(r1), "=r"(r2), "=r"(r3) : "r"(addr));
}
__device__ __forceinline__ void mma_f16(float& c0, float& c1, float& c2, float& c3,
                                        uint32_t a0, uint32_t a1, uint32_t a2, uint32_t a3,
                                        uint32_t b0, uint32_t b1) {
    asm volatile("mma.sync.aligned.m16n8k16.row.col.f32.f16.f16.f32 "
                 "{%0,%1,%2,%3}, {%4,%5,%6,%7}, {%8,%9}, {%0,%1,%2,%3};"
                 : "+f"(c0), "+f"(c1), "+f"(c2), "+f"(c3)
                 : "r"(a0), "r"(a1), "r"(a2), "r"(a3), "r"(b0), "r"(b1));
}

// ---------------- prep: zeroing + fp16 weight packing + x conversion ---------
__global__ void prep(float* pool, float* cnt, int* deg, float* statsA, float* statsB,
                     const float* __restrict__ x, __half* xh,
                     const float* __restrict__ Wq0, const float* __restrict__ Wk0,
                     const float* __restrict__ Wv0, const float* __restrict__ Ws0,
                     const float* __restrict__ bq0, const float* __restrict__ bk0,
                     const float* __restrict__ bv0, const float* __restrict__ bs0,
                     const float* __restrict__ Wq1, const float* __restrict__ Wk1,
                     const float* __restrict__ Wv1, const float* __restrict__ Ws1,
                     const float* __restrict__ bq1, const float* __restrict__ bk1,
                     const float* __restrict__ bv1, const float* __restrict__ bs1,
                     __half* Wph0, float* bp0, __half* Wph1, float* bp1) {
    int gs = gridDim.x * blockDim.x;
    int i0 = blockIdx.x * blockDim.x + threadIdx.x;
    for (int i = i0; i < GG * OUTW; i += gs) pool[i] = 0.f;
    for (int i = i0; i < GG; i += gs) cnt[i] = 0.f;
    for (int i = i0; i < NN; i += gs) deg[i] = 0;
    for (int i = i0; i < 2 * D0; i += gs) statsA[i] = 0.f;
    for (int i = i0; i < 2 * DIMV; i += gs) statsB[i] = 0.f;
    for (int i = i0; i < NN * FIN / 2; i += gs) {
        float2 v = *(const float2*)&x[i * 2];
        *(__half2*)&xh[i * 2] = __floats2half2_rn(v.x, v.y);
    }
    for (int i = i0; i < FIN * 4 * D0; i += gs) {
        int kk = i / (4 * D0), c = i % (4 * D0);
        int sel = c / D0, cc = c % D0;
        const float* W = sel == 0 ? Wq0 : sel == 1 ? Wk0 : sel == 2 ? Wv0 : Ws0;
        Wph0[i] = __float2half_rn(W[kk * D0 + cc]);
    }
    for (int i = i0; i < 4 * D0; i += gs) {
        int sel = i / D0, cc = i % D0;
        const float* b = sel == 0 ? bq0 : sel == 1 ? bk0 : sel == 2 ? bv0 : bs0;
        bp0[i] = b[cc];
    }
    for (int i = i0; i < D0 * 4 * DIMV; i += gs) {
        int kk = i / (4 * DIMV), c = i % (4 * DIMV);
        int sel = c / DIMV, cc = c % DIMV;
        const float* W = sel == 0 ? Wq1 : sel == 1 ? Wk1 : sel == 2 ? Wv1 : Ws1;
        Wph1[i] = __float2half_rn(W[kk * DIMV + cc]);
    }
    for (int i = i0; i < 4 * DIMV; i += gs) {
        int sel = i / DIMV, cc = i % DIMV;
        const float* b = sel == 0 ? bq1 : sel == 1 ? bk1 : sel == 2 ? bv1 : bs1;
        bp1[i] = b[cc];
    }
}

// ---------------- CSR build --------------------------------------------------
__global__ void hist_count(const int* __restrict__ ei, int* deg,
                           const int* __restrict__ batch, float* cnt) {
    int i = blockIdx.x * blockDim.x + threadIdx.x;
    if (i < EE) atomicAdd(&deg[ei[EE + i]], 1);
    if (i < NN) atomicAdd(&cnt[batch[i]], 1.f);
}

__global__ void scan_kernel(int* deg, int* offs) {   // 1 block, 1024 threads
    __shared__ int ps[1024];
    int t = threadIdx.x;
    const int CH = (NN + 1023) / 1024;
    int base = t * CH;
    int sum = 0;
    for (int i = 0; i < CH; i++) {
        int idx = base + i;
        if (idx < NN) sum += deg[idx];
    }
    ps[t] = sum;
    __syncthreads();
    for (int off = 1; off < 1024; off <<= 1) {
        int v = (t >= off) ? ps[t - off] : 0;
        __syncthreads();
        ps[t] += v;
        __syncthreads();
    }
    int run = (t > 0) ? ps[t - 1] : 0;
    for (int i = 0; i < CH; i++) {
        int idx = base + i;
        if (idx < NN) {
            offs[idx] = run;
            run += deg[idx];
            deg[idx] = 0;
        }
    }
}

__global__ void fill_csr(const int* __restrict__ ei, const float* __restrict__ ea,
                         const int* __restrict__ offs, int* deg,
                         int* csrc, float* ca) {
    int e = blockIdx.x * blockDim.x + threadIdx.x;
    if (e >= EE) return;
    int dst = ei[EE + e];
    int slot = offs[dst] + atomicAdd(&deg[dst], 1);
    csrc[slot] = ei[e];
    ca[slot] = ea[e];
}

// ---------------- fp16 tensor-core GEMM, cp.async double-buffered ------------
// [M, 4D] = A @ Wp + bp; col groups: 0 -> float q, 1 -> half k, 2 -> half v,
// 3 -> float skip. 128x128 tile, BK=32, 8 warps (2x4), warp tile 64x32.
#define BM 128
#define BN 128
#define BKH 32
#define APITCH 40    // halves; 80B row stride (16B-aligned, ldmatrix conflict-free)
#define BPITCH 136   // halves; 272B row stride

__global__ __launch_bounds__(256)
void hgemm4(const __half* __restrict__ A, const __half* __restrict__ Wp,
            const float* __restrict__ bp,
            float* __restrict__ Oq, __half* __restrict__ Ok,
            __half* __restrict__ Ov, float* __restrict__ Oo,
            int M, int K, int lda, int D) {
    const int Nc = 4 * D;
    __shared__ __half As[2][BM][APITCH];
    __shared__ __half Bs[2][BKH][BPITCH];

    int t = threadIdx.x;
    int lane = t & 31;
    int warp = t >> 5;
    int wm = warp >> 2;
    int wn = warp & 3;
    int g = lane >> 2;
    int t4 = lane & 3;
    int row0 = blockIdx.y * BM;
    int col0 = blockIdx.x * BN;

    float acc[4][4][4] = {};

    // cp.async chunk mapping (2 chunks each for A and B per thread)
    // A: 512 chunks: row = c>>2, col8 = (c&3)*8
    // B: 512 chunks: row = c>>4, col8 = (c&15)*8
    int a_r0 = t >> 2, a_c0 = (t & 3) * 8;
    int a_r1 = (t + 256) >> 2, a_c1 = ((t + 256) & 3) * 8;
    int b_r0 = t >> 4, b_c0 = (t & 15) * 8;
    int b_r1 = (t + 256) >> 4, b_c1 = ((t + 256) & 15) * 8;

    int a_row_l = lane & 15;
    int a_koff = (lane >> 4) * 8;
    int b_krow_l = ((lane >> 3) & 1) * 8 + (lane & 7);
    int b_noff = (lane >> 4) * 8;

    const int KT = K / BKH;

    auto load_tiles = [&](int st, int k0) {
        int gr0 = row0 + a_r0, gr1 = row0 + a_r1;
        cp_async16(smem_u32(&As[st][a_r0][a_c0]), &A[gr0 * lda + k0 + a_c0],
                   gr0 < M ? 16 : 0);
        cp_async16(smem_u32(&As[st][a_r1][a_c1]), &A[gr1 * lda + k0 + a_c1],
                   gr1 < M ? 16 : 0);
        cp_async16(smem_u32(&Bs[st][b_r0][b_c0]), &Wp[(k0 + b_r0) * Nc + col0 + b_c0], 16);
        cp_async16(smem_u32(&Bs[st][b_r1][b_c1]), &Wp[(k0 + b_r1) * Nc + col0 + b_c1], 16);
    };

    load_tiles(0, 0);
    cp_commit();

    for (int kt = 0; kt < KT; kt++) {
        int st = kt & 1;
        if (kt + 1 < KT) {
            load_tiles(st ^ 1, (kt + 1) * BKH);
            cp_commit();
            asm volatile("cp.async.wait_group 1;");
        } else {
            asm volatile("cp.async.wait_group 0;");
        }
        __syncthreads();

        #pragma unroll
        for (int ks = 0; ks < 2; ks++) {
            int kk = ks * 16;
            uint32_t af[4][4], bf[4][2];
            #pragma unroll
            for (int mt = 0; mt < 4; mt++) {
                int rb = wm * 64 + mt * 16;
                uint32_t addr = smem_u32(&As[st][rb + a_row_l][kk + a_koff]);
                ldsm_x4(af[mt][0], af[mt][1], af[mt][2], af[mt][3], addr);
            }
            #pragma unroll
            for (int p = 0; p < 2; p++) {
                int n0 = wn * 32 + p * 16;
                uint32_t addr = smem_u32(&Bs[st][kk + b_krow_l][n0 + b_noff]);
                ldsm_x4_t(bf[2 * p][0], bf[2 * p][1], bf[2 * p + 1][0], bf[2 * p + 1][1],
                          addr);
            }
            #pragma unroll
            for (int mt = 0; mt < 4; mt++)
                #pragma unroll
                for (int nt = 0; nt < 4; nt++)
                    mma_f16(acc[mt][nt][0], acc[mt][nt][1], acc[mt][nt][2], acc[mt][nt][3],
                            af[mt][0], af[mt][1], af[mt][2], af[mt][3],
                            bf[nt][0], bf[nt][1]);
        }
        __syncthreads();
    }

    #pragma unroll
    for (int nt = 0; nt < 4; nt++) {
        int cg = col0 + wn * 32 + nt * 8;
        int sel = cg / D;
        int cc = cg % D;
        int c0 = cc + 2 * t4;
        float2 bias = *(const float2*)&bp[cg + 2 * t4];
        if (sel == 1 || sel == 2) {
            __half* O = (sel == 1) ? Ok : Ov;
            #pragma unroll
            for (int mt = 0; mt < 4; mt++) {
                int r0 = row0 + wm * 64 + mt * 16 + g;
                if (r0 < M)
                    *(__half2*)&O[r0 * D + c0] =
                        __floats2half2_rn(acc[mt][nt][0] + bias.x, acc[mt][nt][1] + bias.y);
                if (r0 + 8 < M)
                    *(__half2*)&O[(r0 + 8) * D + c0] =
                        __floats2half2_rn(acc[mt][nt][2] + bias.x, acc[mt][nt][3] + bias.y);
            }
        } else {
            float* O = (sel == 0) ? Oq : Oo;
            #pragma unroll
            for (int mt = 0; mt < 4; mt++) {
                int r0 = row0 + wm * 64 + mt * 16 + g;
                if (r0 < M)
                    *(float2*)&O[r0 * D + c0] =
                        make_float2(acc[mt][nt][0] + bias.x, acc[mt][nt][1] + bias.y);
                if (r0 + 8 < M)
                    *(float2*)&O[(r0 + 8) * D + c0] =
                        make_float2(acc[mt][nt][2] + bias.x, acc[mt][nt][3] + bias.y);
            }
        }
    }
}

// ---------------- node aggregation (warp per node, 2-edge pipelined) ---------
template <int D>
__device__ __forceinline__ void loadkv(const __half* __restrict__ kh,
                                       const __half* __restrict__ vh,
                                       int src, int lane, float* kr, float* vr) {
    if constexpr (D == 256) {
        uint2 ku0 = *(const uint2*)&kh[src * D + lane * 4];
        uint2 ku1 = *(const uint2*)&kh[src * D + 128 + lane * 4];
        uint2 vu0 = *(const uint2*)&vh[src * D + lane * 4];
        uint2 vu1 = *(const uint2*)&vh[src * D + 128 + lane * 4];
        float2 f;
        f = __half22float2(*(__half2*)&ku0.x); kr[0] = f.x; kr[1] = f.y;
        f = __half22float2(*(__half2*)&ku0.y); kr[2] = f.x; kr[3] = f.y;
        f = __half22float2(*(__half2*)&ku1.x); kr[4] = f.x; kr[5] = f.y;
        f = __half22float2(*(__half2*)&ku1.y); kr[6] = f.x; kr[7] = f.y;
        f = __half22float2(*(__half2*)&vu0.x); vr[0] = f.x; vr[1] = f.y;
        f = __half22float2(*(__half2*)&vu0.y); vr[2] = f.x; vr[3] = f.y;
        f = __half22float2(*(__half2*)&vu1.x); vr[4] = f.x; vr[5] = f.y;
        f = __half22float2(*(__half2*)&vu1.y); vr[6] = f.x; vr[7] = f.y;
    } else {
        uint32_t ku = *(const uint32_t*)&kh[src * D + lane * 2];
        uint32_t vu = *(const uint32_t*)&vh[src * D + lane * 2];
        float2 f;
        f = __half22float2(*(__half2*)&ku); kr[0] = f.x; kr[1] = f.y;
        f = __half22float2(*(__half2*)&vu); vr[0] = f.x; vr[1] = f.y;
    }
}

template <int D>
__global__ __launch_bounds__(256)
void node_agg(const float* __restrict__ q, const __half* __restrict__ kh,
              const __half* __restrict__ vh, float* __restrict__ o,
              const int* __restrict__ offs, const int* __restrict__ deg,
              const int* __restrict__ csrc, const float* __restrict__ ca,
              const float* __restrict__ We, float* __restrict__ stats, float scale) {
    constexpr int C = D / 32;
    __shared__ float ssu[D], ssq[D];
    int t = threadIdx.x;
    int lane = t & 31;
    for (int i = t; i < D; i += 256) { ssu[i] = 0.f; ssq[i] = 0.f; }
    __syncthreads();

    int col[C];
    if constexpr (D == 256) {
        #pragma unroll
        for (int i = 0; i < 4; i++) { col[i] = lane * 4 + i; col[4 + i] = 128 + lane * 4 + i; }
    } else {
        #pragma unroll
        for (int i = 0; i < C; i++) col[i] = lane * C + i;
    }

    float we[C];
    #pragma unroll
    for (int i = 0; i < C; i++) we[i] = We[col[i]];

    float su[C] = {}, sq[C] = {};

    int wg = blockIdx.x * 8 + (t >> 5);
    int tw = gridDim.x * 8;

    for (int n = wg; n < NN; n += tw) {
        float qr[C], acc[C] = {};
        float s = 0.f;
        if constexpr (D == 256) {
            float4 a0 = *(const float4*)&q[n * D + lane * 4];
            float4 a1 = *(const float4*)&q[n * D + 128 + lane * 4];
            qr[0] = a0.x; qr[1] = a0.y; qr[2] = a0.z; qr[3] = a0.w;
            qr[4] = a1.x; qr[5] = a1.y; qr[6] = a1.z; qr[7] = a1.w;
        } else {
            float2 a0 = *(const float2*)&q[n * D + lane * 2];
            qr[0] = a0.x; qr[1] = a0.y;
        }
        int jb = offs[n], je = jb + deg[n];
        int j = jb;
        for (; j + 2 <= je; j += 2) {
            int s0 = __ldg(&csrc[j]), s1 = __ldg(&csrc[j + 1]);
            float a0 = __ldg(&ca[j]), a1 = __ldg(&ca[j + 1]);
            float kr0[C], vr0[C], kr1[C], vr1[C];
            loadkv<D>(kh, vh, s0, lane, kr0, vr0);
            loadkv<D>(kh, vh, s1, lane, kr1, vr1);
            float pa = 0.f, pb = 0.f;
            #pragma unroll
            for (int i = 0; i < C; i++) {
                pa += qr[i] * fmaf(a0, we[i], kr0[i]);
                pb += qr[i] * fmaf(a1, we[i], kr1[i]);
            }
            #pragma unroll
            for (int off = 16; off > 0; off >>= 1) {
                pa += __shfl_xor_sync(0xffffffffu, pa, off);
                pb += __shfl_xor_sync(0xffffffffu, pb, off);
            }
            float p0 = __expf(pa * scale);
            float p1 = __expf(pb * scale);
            s += p0 + p1;
            #pragma unroll
            for (int i = 0; i < C; i++) {
                acc[i] = fmaf(p0, fmaf(a0, we[i], vr0[i]), acc[i]);
                acc[i] = fmaf(p1, fmaf(a1, we[i], vr1[i]), acc[i]);
            }
        }
        if (j < je) {
            int s0 = __ldg(&csrc[j]);
            float a0 = __ldg(&ca[j]);
            float kr0[C], vr0[C];
            loadkv<D>(kh, vh, s0, lane, kr0, vr0);
            float pa = 0.f;
            #pragma unroll
            for (int i = 0; i < C; i++) pa += qr[i] * fmaf(a0, we[i], kr0[i]);
            #pragma unroll
            for (int off = 16; off > 0; off >>= 1)
                pa += __shfl_xor_sync(0xffffffffu, pa, off);
            float p0 = __expf(pa * scale);
            s += p0;
            #pragma unroll
            for (int i = 0; i < C; i++)
                acc[i] = fmaf(p0, fmaf(a0, we[i], vr0[i]), acc[i]);
        }
        float inv = 1.f / (s + 1e-16f);
        float val[C];
        if constexpr (D == 256) {
            float4 s0 = *(const float4*)&o[n * D + lane * 4];
            float4 s1 = *(const float4*)&o[n * D + 128 + lane * 4];
            val[0] = s0.x + acc[0] * inv; val[1] = s0.y + acc[1] * inv;
            val[2] = s0.z + acc[2] * inv; val[3] = s0.w + acc[3] * inv;
            val[4] = s1.x + acc[4] * inv; val[5] = s1.y + acc[5] * inv;
            val[6] = s1.z + acc[6] * inv; val[7] = s1.w + acc[7] * inv;
            *(float4*)&o[n * D + lane * 4] = make_float4(val[0], val[1], val[2], val[3]);
            *(float4*)&o[n * D + 128 + lane * 4] = make_float4(val[4], val[5], val[6], val[7]);
        } else {
            float2 s0 = *(const float2*)&o[n * D + lane * 2];
            val[0] = s0.x + acc[0] * inv; val[1] = s0.y + acc[1] * inv;
            *(float2*)&o[n * D + lane * 2] = make_float2(val[0], val[1]);
        }
        #pragma unroll
        for (int i = 0; i < C; i++) { su[i] += val[i]; sq[i] += val[i] * val[i]; }
    }

    #pragma unroll
    for (int i = 0; i < C; i++) {
        atomicAdd(&ssu[col[i]], su[i]);
        atomicAdd(&ssq[col[i]], sq[i]);
    }
    __syncthreads();
    for (int i = t; i < D; i += 256) {
        atomicAdd(&stats[i], ssu[i]);
        atomicAdd(&stats[D + i], ssq[i]);
    }
}

// ---------------- batch norm -------------------------------------------------
__global__ void bn_finalize(float* stats, int Nrows, int D) {
    int c = threadIdx.x;
    if (c >= D) return;
    float mu = stats[c] / (float)Nrows;
    float var = stats[D + c] / (float)Nrows - mu * mu;
    stats[c] = mu;
    stats[D + c] = rsqrtf(var + 1e-5f);
}

// normalize; write xs slab (+optional fp16 copy); batched pool accumulation
template <int D>
__global__ void bn_apply(const float* __restrict__ X, const float* __restrict__ stats,
                         const float* __restrict__ gamma, const float* __restrict__ beta,
                         float* __restrict__ xs, __half* __restrict__ hh,
                         float* __restrict__ pool, const int* __restrict__ batch,
                         int col_off) {
    constexpr int CG = D / 4;
    constexpr int RL = 256 / CG;
    constexpr int CHUNK = 16;
    int t = threadIdx.x;
    int cg = t % CG, rl = t / CG;
    int r0 = blockIdx.x * (RL * CHUNK) + rl * CHUNK;
    int c4 = cg * 4;
    float4 mu = *(const float4*)&stats[c4];
    float4 rs = *(const float4*)&stats[D + c4];
    float4 gm = *(const float4*)&gamma[c4];
    float4 bt = *(const float4*)&beta[c4];
    float4 acc = make_float4(0.f, 0.f, 0.f, 0.f);
    int curb = -1;
    for (int i = 0; i < CHUNK; i++) {
        int r = r0 + i;
        if (r >= NN) break;
        int b = __ldg(&batch[r]);
        if (b != curb) {
            if (curb >= 0) red_add_v4(&pool[curb * OUTW + col_off + c4], acc);
            acc = make_float4(0.f, 0.f, 0.f, 0.f);
            curb = b;
        }
        float4 xv = *(const float4*)&X[r * D + c4];
        float4 val;
        val.x = gm.x * (xv.x - mu.x) * rs.x + bt.x;
        val.y = gm.y * (xv.y - mu.y) * rs.y + bt.y;
        val.z = gm.z * (xv.z - mu.z) * rs.z + bt.z;
        val.w = gm.w * (xv.w - mu.w) * rs.w + bt.w;
        *(float4*)&xs[r * OUTW + col_off + c4] = val;
        if (hh) {
            __half2 h0 = __floats2half2_rn(val.x, val.y);
            __half2 h1 = __floats2half2_rn(val.z, val.w);
            *(uint2*)&hh[r * D + c4] = make_uint2(*(uint32_t*)&h0, *(uint32_t*)&h1);
        }
        acc.x += val.x; acc.y += val.y; acc.z += val.z; acc.w += val.w;
    }
    if (curb >= 0) red_add_v4(&pool[curb * OUTW + col_off + c4], acc);
}

__global__ void pool_div(float* pool, const float* __restrict__ cnt) {
    int i = blockIdx.x * blockDim.x + threadIdx.x;
    if (i >= GG * OUTW) return;
    pool[i] /= fmaxf(cnt[i / OUTW], 1.f);
}

// ---------------- launch -----------------------------------------------------
extern "C" void kernel_launch(void* const* d_in, const int* in_sizes, int n_in,
                              void* d_out, int out_size) {
    const float* x     = (const float*)d_in[0];
    const int*   ei    = (const int*)  d_in[1];
    const float* ea    = (const float*)d_in[2];
    const int*   batch = (const int*)  d_in[3];
    const float* Wq0 = (const float*)d_in[4];  const float* bq0 = (const float*)d_in[5];
    const float* Wk0 = (const float*)d_in[6];  const float* bk0 = (const float*)d_in[7];
    const float* Wv0 = (const float*)d_in[8];  const float* bv0 = (const float*)d_in[9];
    const float* We0 = (const float*)d_in[10];
    const float* Ws0 = (const float*)d_in[11]; const float* bs0 = (const float*)d_in[12];
    const float* gamma0 = (const float*)d_in[13]; const float* beta0 = (const float*)d_in[14];
    const float* Wq1 = (const float*)d_in[15]; const float* bq1 = (const float*)d_in[16];
    const float* Wk1 = (const float*)d_in[17]; const float* bk1 = (const float*)d_in[18];
    const float* Wv1 = (const float*)d_in[19]; const float* bv1 = (const float*)d_in[20];
    const float* We1 = (const float*)d_in[21];
    const float* Ws1 = (const float*)d_in[22]; const float* bs1 = (const float*)d_in[23];
    const float* gamma1 = (const float*)d_in[24]; const float* beta1 = (const float*)d_in[25];

    float* out  = (float*)d_out;
    float* pool = out;
    float* xs   = out + GG * OUTW;

    float *q, *o, *statsA, *statsB, *cnt, *bp0, *bp1, *ca;
    __half *kh, *vh, *xh, *hh, *Wph0, *Wph1;
    int *deg, *offs, *csrc;
    cudaGetSymbolAddress((void**)&q, g_q);
    cudaGetSymbolAddress((void**)&kh, g_kh);
    cudaGetSymbolAddress((void**)&vh, g_vh);
    cudaGetSymbolAddress((void**)&o, g_o);
    cudaGetSymbolAddress((void**)&xh, g_xh);
    cudaGetSymbolAddress((void**)&hh, g_hh);
    cudaGetSymbolAddress((void**)&deg, g_deg);
    cudaGetSymbolAddress((void**)&offs, g_offs);
    cudaGetSymbolAddress((void**)&csrc, g_csrc);
    cudaGetSymbolAddress((void**)&ca, g_ca);
    cudaGetSymbolAddress((void**)&statsA, g_statsA);
    cudaGetSymbolAddress((void**)&statsB, g_statsB);
    cudaGetSymbolAddress((void**)&cnt, g_cnt);
    cudaGetSymbolAddress((void**)&Wph0, g_Wph0);
    cudaGetSymbolAddress((void**)&bp0, g_bp0);
    cudaGetSymbolAddress((void**)&Wph1, g_Wph1);
    cudaGetSymbolAddress((void**)&bp1, g_bp1);

    const int TB = 256;

    // 0: prep   1: hist   2: scan   3: gemm L0 (profiled slot)   4: fill_csr
    prep<<<512, TB>>>(pool, cnt, deg, statsA, statsB, x, xh,
                      Wq0, Wk0, Wv0, Ws0, bq0, bk0, bv0, bs0,
                      Wq1, Wk1, Wv1, Ws1, bq1, bk1, bv1, bs1,
                      Wph0, bp0, Wph1, bp1);
    hist_count<<<(EE + TB - 1) / TB, TB>>>(ei, deg, batch, cnt);
    scan_kernel<<<1, 1024>>>(deg, offs);

    dim3 g0(4 * D0 / BN, (NN + BM - 1) / BM);
    hgemm4<<<g0, 256>>>(xh, Wph0, bp0, q, kh, vh, o, NN, FIN, FIN, D0);

    fill_csr<<<(EE + TB - 1) / TB, TB>>>(ei, ea, offs, deg, csrc, ca);

    node_agg<D0><<<1184, 256>>>(q, kh, vh, o, offs, deg, csrc, ca, We0, statsA, 1.f / 16.f);

    bn_finalize<<<1, D0>>>(statsA, NN, D0);
    bn_apply<D0><<<(NN + 63) / 64, 256>>>(o, statsA, gamma0, beta0, xs, hh, pool, batch, 0);

    dim3 g1(4 * DIMV / BN, (NN + BM - 1) / BM);
    hgemm4<<<g1, 256>>>(hh, Wph1, bp1, q, kh, vh, o, NN, D0, D0, DIMV);

    node_agg<DIMV><<<1184, 256>>>(q, kh, vh, o, offs, deg, csrc, ca, We1, statsB, 1.f / 8.f);

    bn_finalize<<<1, DIMV>>>(statsB, NN, DIMV);
    bn_apply<DIMV><<<(NN + 255) / 256, 256>>>(o, statsB, gamma1, beta1, xs, nullptr, pool,
                                              batch, D0);

    pool_div<<<(GG * OUTW + TB - 1) / TB, TB>>>(pool, cnt);
}

// round 8
// speedup vs baseline: 3.5290x; 1.0136x over previous
#include <cuda_runtime.h>
#include <cuda_fp16.h>
#include <cstdint>

#define NN   50000
#define EE   800000
#define FIN  128
#define D0   256
#define DIMV 64
#define GG   256
#define OUTW 320   // D0 + DIMV

// ---------------- scratch (device globals; no allocation) ----------------
__device__ float  g_q[NN * D0];
__device__ __half g_kh[NN * D0];
__device__ __half g_vh[NN * D0];
__device__ float  g_o[NN * D0];
__device__ __half g_xh[NN * FIN];
__device__ __half g_hh[NN * D0];
__device__ int    g_deg[NN];
__device__ int    g_offs[NN];
__device__ int    g_csrc[EE];
__device__ float  g_ca[EE];
__device__ float  g_statsA[2 * D0];
__device__ float  g_statsB[2 * DIMV];
__device__ float  g_cnt[GG];
__device__ __half g_Wph0[FIN * 4 * D0];
__device__ float  g_bp0[4 * D0];
__device__ __half g_Wph1[D0 * 4 * DIMV];
__device__ float  g_bp1[4 * DIMV];

// ---------------- helpers ----------------
__device__ __forceinline__ void red_add_v4(float* ptr, float4 v) {
    asm volatile("red.global.add.v4.f32 [%0], {%1,%2,%3,%4};"
                 :: "l"(ptr), "f"(v.x), "f"(v.y), "f"(v.z), "f"(v.w) : "memory");
}
__device__ __forceinline__ uint32_t smem_u32(const void* p) {
    return (uint32_t)__cvta_generic_to_shared(p);
}
__device__ __forceinline__ void cp_async16(uint32_t dst, const void* src, int src_sz) {
    asm volatile("cp.async.cg.shared.global [%0], [%1], 16, %2;"
                 :: "r"(dst), "l"(src), "r"(src_sz));
}
__device__ __forceinline__ void cp_commit() {
    asm volatile("cp.async.commit_group;");
}
__device__ __forceinline__ void ldsm_x4(uint32_t& r0, uint32_t& r1, uint32_t& r2,
                                        uint32_t& r3, uint32_t addr) {
    asm volatile("ldmatrix.sync.aligned.m8n8.x4.shared.b16 {%0,%1,%2,%3}, [%4];"
                 : "=r"(r0), "=r"(r1), "=r"(r2), "=r"(r3) : "r"(addr));
}
__device__ __forceinline__ void ldsm_x4_t(uint32_t& r0, uint32_t& r1, uint32_t& r2,
                                          uint32_t& r3, uint32_t addr) {
    asm volatile("ldmatrix.sync.aligned.m8n8.x4.trans.shared.b16 {%0,%1,%2,%3}, [%4];"
                 : "=r"(r0), "=r"(r1), "=r"(r2), "=r"(r3) : "r"(addr));
}
__device__ __forceinline__ void mma_f16(float& c0, float& c1, float& c2, float& c3,
                                        uint32_t a0, uint32_t a1, uint32_t a2, uint32_t a3,
                                        uint32_t b0, uint32_t b1) {
    asm volatile("mma.sync.aligned.m16n8k16.row.col.f32.f16.f16.f32 "
                 "{%0,%1,%2,%3}, {%4,%5,%6,%7}, {%8,%9}, {%0,%1,%2,%3};"
                 : "+f"(c0), "+f"(c1), "+f"(c2), "+f"(c3)
                 : "r"(a0), "r"(a1), "r"(a2), "r"(a3), "r"(b0), "r"(b1));
}

// ---------------- prep: zeroing + fp16 weight packing + x conversion ---------
__global__ void prep(float* pool, float* cnt, int* deg, float* statsA, float* statsB,
                     const float* __restrict__ x, __half* xh,
                     const float* __restrict__ Wq0, const float* __restrict__ Wk0,
                     const float* __restrict__ Wv0, const float* __restrict__ Ws0,
                     const float* __restrict__ bq0, const float* __restrict__ bk0,
                     const float* __restrict__ bv0, const float* __restrict__ bs0,
                     const float* __restrict__ Wq1, const float* __restrict__ Wk1,
                     const float* __restrict__ Wv1, const float* __restrict__ Ws1,
                     const float* __restrict__ bq1, const float* __restrict__ bk1,
                     const float* __restrict__ bv1, const float* __restrict__ bs1,
                     __half* Wph0, float* bp0, __half* Wph1, float* bp1) {
    int gs = gridDim.x * blockDim.x;
    int i0 = blockIdx.x * blockDim.x + threadIdx.x;
    for (int i = i0; i < GG * OUTW; i += gs) pool[i] = 0.f;
    for (int i = i0; i < GG; i += gs) cnt[i] = 0.f;
    for (int i = i0; i < NN; i += gs) deg[i] = 0;
    for (int i = i0; i < 2 * D0; i += gs) statsA[i] = 0.f;
    for (int i = i0; i < 2 * DIMV; i += gs) statsB[i] = 0.f;
    for (int i = i0; i < NN * FIN / 2; i += gs) {
        float2 v = *(const float2*)&x[i * 2];
        *(__half2*)&xh[i * 2] = __floats2half2_rn(v.x, v.y);
    }
    for (int i = i0; i < FIN * 4 * D0; i += gs) {
        int kk = i / (4 * D0), c = i % (4 * D0);
        int sel = c / D0, cc = c % D0;
        const float* W = sel == 0 ? Wq0 : sel == 1 ? Wk0 : sel == 2 ? Wv0 : Ws0;
        Wph0[i] = __float2half_rn(W[kk * D0 + cc]);
    }
    for (int i = i0; i < 4 * D0; i += gs) {
        int sel = i / D0, cc = i % D0;
        const float* b = sel == 0 ? bq0 : sel == 1 ? bk0 : sel == 2 ? bv0 : bs0;
        bp0[i] = b[cc];
    }
    for (int i = i0; i < D0 * 4 * DIMV; i += gs) {
        int kk = i / (4 * DIMV), c = i % (4 * DIMV);
        int sel = c / DIMV, cc = c % DIMV;
        const float* W = sel == 0 ? Wq1 : sel == 1 ? Wk1 : sel == 2 ? Wv1 : Ws1;
        Wph1[i] = __float2half_rn(W[kk * DIMV + cc]);
    }
    for (int i = i0; i < 4 * DIMV; i += gs) {
        int sel = i / DIMV, cc = i % DIMV;
        const float* b = sel == 0 ? bq1 : sel == 1 ? bk1 : sel == 2 ? bv1 : bs1;
        bp1[i] = b[cc];
    }
}

// ---------------- CSR build --------------------------------------------------
__global__ void hist_count(const int* __restrict__ ei, int* deg,
                           const int* __restrict__ batch, float* cnt) {
    int i = blockIdx.x * blockDim.x + threadIdx.x;
    if (i < EE) atomicAdd(&deg[ei[EE + i]], 1);
    if (i < NN) atomicAdd(&cnt[batch[i]], 1.f);
}

__global__ void scan_kernel(int* deg, int* offs) {   // 1 block, 1024 threads
    __shared__ int ps[1024];
    int t = threadIdx.x;
    const int CH = (NN + 1023) / 1024;
    int base = t * CH;
    int sum = 0;
    for (int i = 0; i < CH; i++) {
        int idx = base + i;
        if (idx < NN) sum += deg[idx];
    }
    ps[t] = sum;
    __syncthreads();
    for (int off = 1; off < 1024; off <<= 1) {
        int v = (t >= off) ? ps[t - off] : 0;
        __syncthreads();
        ps[t] += v;
        __syncthreads();
    }
    int run = (t > 0) ? ps[t - 1] : 0;
    for (int i = 0; i < CH; i++) {
        int idx = base + i;
        if (idx < NN) {
            offs[idx] = run;
            run += deg[idx];
            deg[idx] = 0;
        }
    }
}

__global__ void fill_csr(const int* __restrict__ ei, const float* __restrict__ ea,
                         const int* __restrict__ offs, int* deg,
                         int* csrc, float* ca) {
    int e = blockIdx.x * blockDim.x + threadIdx.x;
    if (e >= EE) return;
    int dst = ei[EE + e];
    int slot = offs[dst] + atomicAdd(&deg[dst], 1);
    csrc[slot] = ei[e];
    ca[slot] = ea[e];
}

// ---------------- fp16 tensor-core GEMM, cp.async double-buffered ------------
#define BM 128
#define BN 128
#define BKH 32
#define APITCH 40
#define BPITCH 136

__global__ __launch_bounds__(256)
void hgemm4(const __half* __restrict__ A, const __half* __restrict__ Wp,
            const float* __restrict__ bp,
            float* __restrict__ Oq, __half* __restrict__ Ok,
            __half* __restrict__ Ov, float* __restrict__ Oo,
            int M, int K, int lda, int D) {
    const int Nc = 4 * D;
    __shared__ __half As[2][BM][APITCH];
    __shared__ __half Bs[2][BKH][BPITCH];

    int t = threadIdx.x;
    int lane = t & 31;
    int warp = t >> 5;
    int wm = warp >> 2;
    int wn = warp & 3;
    int g = lane >> 2;
    int t4 = lane & 3;
    int row0 = blockIdx.y * BM;
    int col0 = blockIdx.x * BN;

    float acc[4][4][4] = {};

    int a_r0 = t >> 2, a_c0 = (t & 3) * 8;
    int a_r1 = (t + 256) >> 2, a_c1 = ((t + 256) & 3) * 8;
    int b_r0 = t >> 4, b_c0 = (t & 15) * 8;
    int b_r1 = (t + 256) >> 4, b_c1 = ((t + 256) & 15) * 8;

    int a_row_l = lane & 15;
    int a_koff = (lane >> 4) * 8;
    int b_krow_l = ((lane >> 3) & 1) * 8 + (lane & 7);
    int b_noff = (lane >> 4) * 8;

    const int KT = K / BKH;

    auto load_tiles = [&](int st, int k0) {
        int gr0 = row0 + a_r0, gr1 = row0 + a_r1;
        cp_async16(smem_u32(&As[st][a_r0][a_c0]), &A[gr0 * lda + k0 + a_c0],
                   gr0 < M ? 16 : 0);
        cp_async16(smem_u32(&As[st][a_r1][a_c1]), &A[gr1 * lda + k0 + a_c1],
                   gr1 < M ? 16 : 0);
        cp_async16(smem_u32(&Bs[st][b_r0][b_c0]), &Wp[(k0 + b_r0) * Nc + col0 + b_c0], 16);
        cp_async16(smem_u32(&Bs[st][b_r1][b_c1]), &Wp[(k0 + b_r1) * Nc + col0 + b_c1], 16);
    };

    load_tiles(0, 0);
    cp_commit();

    for (int kt = 0; kt < KT; kt++) {
        int st = kt & 1;
        if (kt + 1 < KT) {
            load_tiles(st ^ 1, (kt + 1) * BKH);
            cp_commit();
            asm volatile("cp.async.wait_group 1;");
        } else {
            asm volatile("cp.async.wait_group 0;");
        }
        __syncthreads();

        #pragma unroll
        for (int ks = 0; ks < 2; ks++) {
            int kk = ks * 16;
            uint32_t af[4][4], bf[4][2];
            #pragma unroll
            for (int mt = 0; mt < 4; mt++) {
                int rb = wm * 64 + mt * 16;
                uint32_t addr = smem_u32(&As[st][rb + a_row_l][kk + a_koff]);
                ldsm_x4(af[mt][0], af[mt][1], af[mt][2], af[mt][3], addr);
            }
            #pragma unroll
            for (int p = 0; p < 2; p++) {
                int n0 = wn * 32 + p * 16;
                uint32_t addr = smem_u32(&Bs[st][kk + b_krow_l][n0 + b_noff]);
                ldsm_x4_t(bf[2 * p][0], bf[2 * p][1], bf[2 * p + 1][0], bf[2 * p + 1][1],
                          addr);
            }
            #pragma unroll
            for (int mt = 0; mt < 4; mt++)
                #pragma unroll
                for (int nt = 0; nt < 4; nt++)
                    mma_f16(acc[mt][nt][0], acc[mt][nt][1], acc[mt][nt][2], acc[mt][nt][3],
                            af[mt][0], af[mt][1], af[mt][2], af[mt][3],
                            bf[nt][0], bf[nt][1]);
        }
        __syncthreads();
    }

    #pragma unroll
    for (int nt = 0; nt < 4; nt++) {
        int cg = col0 + wn * 32 + nt * 8;
        int sel = cg / D;
        int cc = cg % D;
        int c0 = cc + 2 * t4;
        float2 bias = *(const float2*)&bp[cg + 2 * t4];
        if (sel == 1 || sel == 2) {
            __half* O = (sel == 1) ? Ok : Ov;
            #pragma unroll
            for (int mt = 0; mt < 4; mt++) {
                int r0 = row0 + wm * 64 + mt * 16 + g;
                if (r0 < M)
                    *(__half2*)&O[r0 * D + c0] =
                        __floats2half2_rn(acc[mt][nt][0] + bias.x, acc[mt][nt][1] + bias.y);
                if (r0 + 8 < M)
                    *(__half2*)&O[(r0 + 8) * D + c0] =
                        __floats2half2_rn(acc[mt][nt][2] + bias.x, acc[mt][nt][3] + bias.y);
            }
        } else {
            float* O = (sel == 0) ? Oq : Oo;
            #pragma unroll
            for (int mt = 0; mt < 4; mt++) {
                int r0 = row0 + wm * 64 + mt * 16 + g;
                if (r0 < M)
                    *(float2*)&O[r0 * D + c0] =
                        make_float2(acc[mt][nt][0] + bias.x, acc[mt][nt][1] + bias.y);
                if (r0 + 8 < M)
                    *(float2*)&O[(r0 + 8) * D + c0] =
                        make_float2(acc[mt][nt][2] + bias.x, acc[mt][nt][3] + bias.y);
            }
        }
    }
}

// ---------------- node aggregation -------------------------------------------
// warp per node; lane owns D/32 contiguous columns (16B for D=256).
// logits: q·(k+a·We) = q·k + a*(q·We)  [q·We once per node]
// agg:    Σp(v+a·We) = Σp·v + (Σp·a)·We [We term once per node]
template <int D>
__device__ __forceinline__ void loadrow(const __half* __restrict__ base, int src,
                                        int lane, float* r) {
    if constexpr (D == 256) {
        uint4 u = *(const uint4*)&base[src * D + lane * 8];
        float2 f;
        f = __half22float2(*(__half2*)&u.x); r[0] = f.x; r[1] = f.y;
        f = __half22float2(*(__half2*)&u.y); r[2] = f.x; r[3] = f.y;
        f = __half22float2(*(__half2*)&u.z); r[4] = f.x; r[5] = f.y;
        f = __half22float2(*(__half2*)&u.w); r[6] = f.x; r[7] = f.y;
    } else {
        uint32_t u = *(const uint32_t*)&base[src * D + lane * 2];
        float2 f = __half22float2(*(__half2*)&u);
        r[0] = f.x; r[1] = f.y;
    }
}

template <int D>
__global__ __launch_bounds__(256)
void node_agg(const float* __restrict__ q, const __half* __restrict__ kh,
              const __half* __restrict__ vh, float* __restrict__ o,
              const int* __restrict__ offs, const int* __restrict__ deg,
              const int* __restrict__ csrc, const float* __restrict__ ca,
              const float* __restrict__ We, float* __restrict__ stats, float scale) {
    constexpr int C = D / 32;
    __shared__ float ssu[D], ssq[D];
    int t = threadIdx.x;
    int lane = t & 31;
    for (int i = t; i < D; i += 256) { ssu[i] = 0.f; ssq[i] = 0.f; }
    __syncthreads();

    int c0 = lane * C;    // contiguous column block per lane
    float we[C];
    #pragma unroll
    for (int i = 0; i < C; i++) we[i] = We[c0 + i];

    float su[C] = {}, sq[C] = {};

    int wg = blockIdx.x * 8 + (t >> 5);
    int tw = gridDim.x * 8;

    for (int n = wg; n < NN; n += tw) {
        float qr[C], acc[C] = {};
        if constexpr (D == 256) {
            float4 a0 = *(const float4*)&q[n * D + c0];
            float4 a1 = *(const float4*)&q[n * D + c0 + 4];
            qr[0] = a0.x; qr[1] = a0.y; qr[2] = a0.z; qr[3] = a0.w;
            qr[4] = a1.x; qr[5] = a1.y; qr[6] = a1.z; qr[7] = a1.w;
        } else {
            float2 a0 = *(const float2*)&q[n * D + c0];
            qr[0] = a0.x; qr[1] = a0.y;
        }
        // q·We once per node
        float qwe = 0.f;
        #pragma unroll
        for (int i = 0; i < C; i++) qwe += qr[i] * we[i];
        #pragma unroll
        for (int off = 16; off > 0; off >>= 1)
            qwe += __shfl_xor_sync(0xffffffffu, qwe, off);

        float s = 0.f, pa = 0.f;
        int jb = offs[n], je = jb + deg[n];
        int j = jb;
        for (; j + 4 <= je; j += 4) {
            int e0 = __ldg(&csrc[j]),     e1 = __ldg(&csrc[j + 1]);
            int e2 = __ldg(&csrc[j + 2]), e3 = __ldg(&csrc[j + 3]);
            float a0 = __ldg(&ca[j]),     a1 = __ldg(&ca[j + 1]);
            float a2 = __ldg(&ca[j + 2]), a3 = __ldg(&ca[j + 3]);
            float k0[C], k1[C], k2[C], k3[C];
            float v0[C], v1[C], v2[C], v3[C];
            loadrow<D>(kh, e0, lane, k0); loadrow<D>(kh, e1, lane, k1);
            loadrow<D>(kh, e2, lane, k2); loadrow<D>(kh, e3, lane, k3);
            loadrow<D>(vh, e0, lane, v0); loadrow<D>(vh, e1, lane, v1);
            loadrow<D>(vh, e2, lane, v2); loadrow<D>(vh, e3, lane, v3);
            float d0 = 0.f, d1 = 0.f, d2 = 0.f, d3 = 0.f;
            #pragma unroll
            for (int i = 0; i < C; i++) {
                d0 = fmaf(qr[i], k0[i], d0); d1 = fmaf(qr[i], k1[i], d1);
                d2 = fmaf(qr[i], k2[i], d2); d3 = fmaf(qr[i], k3[i], d3);
            }
            #pragma unroll
            for (int off = 16; off > 0; off >>= 1) {
                d0 += __shfl_xor_sync(0xffffffffu, d0, off);
                d1 += __shfl_xor_sync(0xffffffffu, d1, off);
                d2 += __shfl_xor_sync(0xffffffffu, d2, off);
                d3 += __shfl_xor_sync(0xffffffffu, d3, off);
            }
            float p0 = __expf((d0 + a0 * qwe) * scale);
            float p1 = __expf((d1 + a1 * qwe) * scale);
            float p2 = __expf((d2 + a2 * qwe) * scale);
            float p3 = __expf((d3 + a3 * qwe) * scale);
            s += (p0 + p1) + (p2 + p3);
            pa = fmaf(p0, a0, pa); pa = fmaf(p1, a1, pa);
            pa = fmaf(p2, a2, pa); pa = fmaf(p3, a3, pa);
            #pragma unroll
            for (int i = 0; i < C; i++) {
                float z = fmaf(p0, v0[i], acc[i]);
                z = fmaf(p1, v1[i], z);
                z = fmaf(p2, v2[i], z);
                acc[i] = fmaf(p3, v3[i], z);
            }
        }
        for (; j < je; j++) {
            int e0 = __ldg(&csrc[j]);
            float a0 = __ldg(&ca[j]);
            float k0[C], v0[C];
            loadrow<D>(kh, e0, lane, k0);
            loadrow<D>(vh, e0, lane, v0);
            float d0 = 0.f;
            #pragma unroll
            for (int i = 0; i < C; i++) d0 = fmaf(qr[i], k0[i], d0);
            #pragma unroll
            for (int off = 16; off > 0; off >>= 1)
                d0 += __shfl_xor_sync(0xffffffffu, d0, off);
            float p0 = __expf((d0 + a0 * qwe) * scale);
            s += p0;
            pa = fmaf(p0, a0, pa);
            #pragma unroll
            for (int i = 0; i < C; i++) acc[i] = fmaf(p0, v0[i], acc[i]);
        }
        float inv = 1.f / (s + 1e-16f);
        float val[C];
        if constexpr (D == 256) {
            float4 s0 = *(const float4*)&o[n * D + c0];
            float4 s1 = *(const float4*)&o[n * D + c0 + 4];
            float sk[8] = {s0.x, s0.y, s0.z, s0.w, s1.x, s1.y, s1.z, s1.w};
            #pragma unroll
            for (int i = 0; i < 8; i++)
                val[i] = sk[i] + (acc[i] + pa * we[i]) * inv;
            *(float4*)&o[n * D + c0] = make_float4(val[0], val[1], val[2], val[3]);
            *(float4*)&o[n * D + c0 + 4] = make_float4(val[4], val[5], val[6], val[7]);
        } else {
            float2 s0 = *(const float2*)&o[n * D + c0];
            val[0] = s0.x + (acc[0] + pa * we[0]) * inv;
            val[1] = s0.y + (acc[1] + pa * we[1]) * inv;
            *(float2*)&o[n * D + c0] = make_float2(val[0], val[1]);
        }
        #pragma unroll
        for (int i = 0; i < C; i++) { su[i] += val[i]; sq[i] += val[i] * val[i]; }
    }

    #pragma unroll
    for (int i = 0; i < C; i++) {
        atomicAdd(&ssu[c0 + i], su[i]);
        atomicAdd(&ssq[c0 + i], sq[i]);
    }
    __syncthreads();
    for (int i = t; i < D; i += 256) {
        atomicAdd(&stats[i], ssu[i]);
        atomicAdd(&stats[D + i], ssq[i]);
    }
}

// ---------------- batch norm -------------------------------------------------
__global__ void bn_finalize(float* stats, int Nrows, int D) {
    int c = threadIdx.x;
    if (c >= D) return;
    float mu = stats[c] / (float)Nrows;
    float var = stats[D + c] / (float)Nrows - mu * mu;
    stats[c] = mu;
    stats[D + c] = rsqrtf(var + 1e-5f);
}

template <int D>
__global__ void bn_apply(const float* __restrict__ X, const float* __restrict__ stats,
                         const float* __restrict__ gamma, const float* __restrict__ beta,
                         float* __restrict__ xs, __half* __restrict__ hh,
                         float* __restrict__ pool, const int* __restrict__ batch,
                         int col_off) {
    constexpr int CG = D / 4;
    constexpr int RL = 256 / CG;
    constexpr int CHUNK = 16;
    int t = threadIdx.x;
    int cg = t % CG, rl = t / CG;
    int r0 = blockIdx.x * (RL * CHUNK) + rl * CHUNK;
    int c4 = cg * 4;
    float4 mu = *(const float4*)&stats[c4];
    float4 rs = *(const float4*)&stats[D + c4];
    float4 gm = *(const float4*)&gamma[c4];
    float4 bt = *(const float4*)&beta[c4];
    float4 acc = make_float4(0.f, 0.f, 0.f, 0.f);
    int curb = -1;
    for (int i = 0; i < CHUNK; i++) {
        int r = r0 + i;
        if (r >= NN) break;
        int b = __ldg(&batch[r]);
        if (b != curb) {
            if (curb >= 0) red_add_v4(&pool[curb * OUTW + col_off + c4], acc);
            acc = make_float4(0.f, 0.f, 0.f, 0.f);
            curb = b;
        }
        float4 xv = *(const float4*)&X[r * D + c4];
        float4 val;
        val.x = gm.x * (xv.x - mu.x) * rs.x + bt.x;
        val.y = gm.y * (xv.y - mu.y) * rs.y + bt.y;
        val.z = gm.z * (xv.z - mu.z) * rs.z + bt.z;
        val.w = gm.w * (xv.w - mu.w) * rs.w + bt.w;
        *(float4*)&xs[r * OUTW + col_off + c4] = val;
        if (hh) {
            __half2 h0 = __floats2half2_rn(val.x, val.y);
            __half2 h1 = __floats2half2_rn(val.z, val.w);
            *(uint2*)&hh[r * D + c4] = make_uint2(*(uint32_t*)&h0, *(uint32_t*)&h1);
        }
        acc.x += val.x; acc.y += val.y; acc.z += val.z; acc.w += val.w;
    }
    if (curb >= 0) red_add_v4(&pool[curb * OUTW + col_off + c4], acc);
}

__global__ void pool_div(float* pool, const float* __restrict__ cnt) {
    int i = blockIdx.x * blockDim.x + threadIdx.x;
    if (i >= GG * OUTW) return;
    pool[i] /= fmaxf(cnt[i / OUTW], 1.f);
}

// ---------------- launch -----------------------------------------------------
extern "C" void kernel_launch(void* const* d_in, const int* in_sizes, int n_in,
                              void* d_out, int out_size) {
    const float* x     = (const float*)d_in[0];
    const int*   ei    = (const int*)  d_in[1];
    const float* ea    = (const float*)d_in[2];
    const int*   batch = (const int*)  d_in[3];
    const float* Wq0 = (const float*)d_in[4];  const float* bq0 = (const float*)d_in[5];
    const float* Wk0 = (const float*)d_in[6];  const float* bk0 = (const float*)d_in[7];
    const float* Wv0 = (const float*)d_in[8];  const float* bv0 = (const float*)d_in[9];
    const float* We0 = (const float*)d_in[10];
    const float* Ws0 = (const float*)d_in[11]; const float* bs0 = (const float*)d_in[12];
    const float* gamma0 = (const float*)d_in[13]; const float* beta0 = (const float*)d_in[14];
    const float* Wq1 = (const float*)d_in[15]; const float* bq1 = (const float*)d_in[16];
    const float* Wk1 = (const float*)d_in[17]; const float* bk1 = (const float*)d_in[18];
    const float* Wv1 = (const float*)d_in[19]; const float* bv1 = (const float*)d_in[20];
    const float* We1 = (const float*)d_in[21];
    const float* Ws1 = (const float*)d_in[22]; const float* bs1 = (const float*)d_in[23];
    const float* gamma1 = (const float*)d_in[24]; const float* beta1 = (const float*)d_in[25];

    float* out  = (float*)d_out;
    float* pool = out;
    float* xs   = out + GG * OUTW;

    float *q, *o, *statsA, *statsB, *cnt, *bp0, *bp1, *ca;
    __half *kh, *vh, *xh, *hh, *Wph0, *Wph1;
    int *deg, *offs, *csrc;
    cudaGetSymbolAddress((void**)&q, g_q);
    cudaGetSymbolAddress((void**)&kh, g_kh);
    cudaGetSymbolAddress((void**)&vh, g_vh);
    cudaGetSymbolAddress((void**)&o, g_o);
    cudaGetSymbolAddress((void**)&xh, g_xh);
    cudaGetSymbolAddress((void**)&hh, g_hh);
    cudaGetSymbolAddress((void**)&deg, g_deg);
    cudaGetSymbolAddress((void**)&offs, g_offs);
    cudaGetSymbolAddress((void**)&csrc, g_csrc);
    cudaGetSymbolAddress((void**)&ca, g_ca);
    cudaGetSymbolAddress((void**)&statsA, g_statsA);
    cudaGetSymbolAddress((void**)&statsB, g_statsB);
    cudaGetSymbolAddress((void**)&cnt, g_cnt);
    cudaGetSymbolAddress((void**)&Wph0, g_Wph0);
    cudaGetSymbolAddress((void**)&bp0, g_bp0);
    cudaGetSymbolAddress((void**)&Wph1, g_Wph1);
    cudaGetSymbolAddress((void**)&bp1, g_bp1);

    const int TB = 256;

    // 0: prep   1: hist   2: scan   3: gemm L0 (profiled slot)   4: fill_csr
    prep<<<512, TB>>>(pool, cnt, deg, statsA, statsB, x, xh,
                      Wq0, Wk0, Wv0, Ws0, bq0, bk0, bv0, bs0,
                      Wq1, Wk1, Wv1, Ws1, bq1, bk1, bv1, bs1,
                      Wph0, bp0, Wph1, bp1);
    hist_count<<<(EE + TB - 1) / TB, TB>>>(ei, deg, batch, cnt);
    scan_kernel<<<1, 1024>>>(deg, offs);

    dim3 g0(4 * D0 / BN, (NN + BM - 1) / BM);
    hgemm4<<<g0, 256>>>(xh, Wph0, bp0, q, kh, vh, o, NN, FIN, FIN, D0);

    fill_csr<<<(EE + TB - 1) / TB, TB>>>(ei, ea, offs, deg, csrc, ca);

    node_agg<D0><<<1184, 256>>>(q, kh, vh, o, offs, deg, csrc, ca, We0, statsA, 1.f / 16.f);

    bn_finalize<<<1, D0>>>(statsA, NN, D0);
    bn_apply<D0><<<(NN + 63) / 64, 256>>>(o, statsA, gamma0, beta0, xs, hh, pool, batch, 0);

    dim3 g1(4 * DIMV / BN, (NN + BM - 1) / BM);
    hgemm4<<<g1, 256>>>(hh, Wph1, bp1, q, kh, vh, o, NN, D0, D0, DIMV);

    node_agg<DIMV><<<1184, 256>>>(q, kh, vh, o, offs, deg, csrc, ca, We1, statsB, 1.f / 8.f);

    bn_finalize<<<1, DIMV>>>(statsB, NN, DIMV);
    bn_apply<DIMV><<<(NN + 255) / 256, 256>>>(o, statsB, gamma1, beta1, xs, nullptr, pool,
                                              batch, D0);

    pool_div<<<(GG * OUTW + TB - 1) / TB, TB>>>(pool, cnt);
}